// round 13
// baseline (speedup 1.0000x reference)
#include <cuda_runtime.h>
#include <cuda_bf16.h>
#include <math.h>

#define BR 4
#define BB 32
#define TT 1024
#define HH 64
#define DD 128
#define NN 16
#define KK 4
#define RR 4
#define EE 32
#define LL 3
#define CH 16          // scan chunks
#define CS 64          // steps per chunk
#define MAXN 0.996f

typedef unsigned long long u64;

// ---------------- f32x2 packed-FMA helpers (sm_103a FFMA2 path) ----------------
__device__ __forceinline__ u64 pk2(float x, float y) {
    u64 r; asm("mov.b64 %0, {%1, %2};" : "=l"(r) : "f"(x), "f"(y)); return r;
}
__device__ __forceinline__ float2 upk2(u64 v) {
    float2 r; asm("mov.b64 {%0, %1}, %2;" : "=f"(r.x), "=f"(r.y) : "l"(v)); return r;
}
__device__ __forceinline__ void fma2(u64& d, u64 a, u64 b) {
    asm("fma.rn.f32x2 %0, %1, %2, %0;" : "+l"(d) : "l"(a), "l"(b));
}
__device__ __forceinline__ u64 mul2(u64 a, u64 b) {
    u64 r; asm("mul.rn.f32x2 %0, %1, %2;" : "=l"(r) : "l"(a), "l"(b)); return r;
}
__device__ __forceinline__ float ex2f(float x) {
    float r; asm("ex2.approx.f32 %0, %1;" : "=f"(r) : "f"(x)); return r;
}
__device__ __forceinline__ float lg2f(float x) {
    float r; asm("lg2.approx.f32 %0, %1;" : "=f"(r) : "f"(x)); return r;
}
__device__ __forceinline__ float rcpf(float x) {
    float r; asm("rcp.approx.f32 %0, %1;" : "=f"(r) : "f"(x)); return r;
}
#define F_LOG2E 1.4426950408889634f
__device__ __forceinline__ float fsilu(float v) {
    return v * rcpf(1.f + ex2f(-v * F_LOG2E));
}
__device__ __forceinline__ float ftanh(float x) {
    // tanh(x) = 1 - 2/(exp(2x)+1); saturates correctly for |x| large
    return 1.f - 2.f * rcpf(ex2f(2.f * F_LOG2E * x) + 1.f);
}

union F4U {
    float4 f;
    struct { u64 lo, hi; } d;
};

// ---------------- scratch (device globals; no allocation allowed) ----------------
__device__ float g_h[2][(size_t)BR*BB*TT*HH];
__device__ float g_xr[(size_t)BR*BB*TT*DD];
__device__ float g_z [(size_t)BR*BB*TT*DD];
__device__ float g_u [(size_t)BR*BB*TT*DD];
__device__ float g_xdbl[(size_t)BR*BB*TT*36];
__device__ float g_y [(size_t)BR*BB*TT*DD];
// chunked-scan carries: [bb][chunk][d][n]
__device__ float g_hfin[(size_t)BR*BB*CH*DD*NN];
__device__ float g_pfin[(size_t)BR*BB*CH*DD*NN];
__device__ float g_hin [(size_t)BR*BB*CH*DD*NN];
// rank-1 layer-0 folded weights
__device__ float g_v1[BR * 2 * DD];
__device__ float g_v0[BR * 2 * DD];

__device__ __forceinline__ float wsum(float v) {
    #pragma unroll
    for (int o = 16; o; o >>= 1) v += __shfl_xor_sync(0xffffffffu, v, o);
    return v;
}

// ---------------- k_prep0: fold embed into layer-0 in_proj (rank-1) ----------------
__global__ void k_prep0(const float* __restrict__ inW_all,
                        const float* __restrict__ iW, const float* __restrict__ ib) {
    int br = blockIdx.x, dd = threadIdx.x;
    const float* Wb = inW_all + ((size_t)(br * LL) * 2 * DD + dd) * HH;
    const float* iwp = iW + br * HH;
    const float* ibp = ib + br * HH;
    float v1 = 0.f, v0 = 0.f;
    #pragma unroll
    for (int h = 0; h < HH; h++) {
        float w = Wb[h];
        v1 += iwp[h] * w;
        v0 += ibp[h] * w;
    }
    g_v1[br * 2 * DD + dd] = v1;
    g_v0[br * 2 * DD + dd] = v0;
}

// ---------------- k_inproj: row-packed FFMA2 (layers 1,2) ----------------
__global__ void k_inproj(const float* __restrict__ inW_all, int l, int src) {
    extern __shared__ float sm[];
    float* sHt = sm;              // [64][68] transposed
    float* sW  = sm + 64 * 68;    // [64][132]
    int br = blockIdx.z, b = blockIdx.y, t0 = blockIdx.x * 64;
    int tid = threadIdx.x;
    const float* Wb = inW_all + (size_t)((br * LL + l) * 2 * DD) * HH;
    const float* hb = g_h[src] + ((size_t)(br * BB + b) * TT + t0) * HH;
    for (int i = tid; i < 4096; i += 256) sHt[(i & 63) * 68 + (i >> 6)] = hb[i];

    size_t outbase = ((size_t)(br * BB + b) * TT + t0) * DD;
    int rowg = tid & 7, colg = tid >> 3;
    for (int dc = 0; dc < 2; dc++) {
        __syncthreads();
        int d0 = dc * 128;
        for (int i = tid; i < 8192; i += 256) {
            int k = i & 63, dl = i >> 6;
            sW[k * 132 + dl] = Wb[(size_t)(d0 + dl) * HH + k];
        }
        __syncthreads();
        u64 acc[4][4];
        #pragma unroll
        for (int i = 0; i < 4; i++)
            #pragma unroll
            for (int j = 0; j < 4; j++) acc[i][j] = 0ull;
        #pragma unroll 4
        for (int k = 0; k < 64; k++) {
            F4U hA, hB;
            hA.f = *(const float4*)&sHt[k * 68 + rowg * 8];
            hB.f = *(const float4*)&sHt[k * 68 + rowg * 8 + 4];
            u64 rp[4] = {hA.d.lo, hA.d.hi, hB.d.lo, hB.d.hi};
            float4 w = *(const float4*)&sW[k * 132 + colg * 4];
            u64 wb[4] = {pk2(w.x, w.x), pk2(w.y, w.y), pk2(w.z, w.z), pk2(w.w, w.w)};
            #pragma unroll
            for (int i = 0; i < 4; i++)
                #pragma unroll
                for (int j = 0; j < 4; j++)
                    fma2(acc[i][j], rp[i], wb[j]);
        }
        float* dst = (dc == 0) ? g_xr : g_z;
        #pragma unroll
        for (int i = 0; i < 4; i++) {
            float2 c0 = upk2(acc[i][0]), c1 = upk2(acc[i][1]);
            float2 c2 = upk2(acc[i][2]), c3 = upk2(acc[i][3]);
            *(float4*)&dst[outbase + (size_t)(rowg * 8 + 2 * i) * DD + colg * 4] =
                make_float4(c0.x, c1.x, c2.x, c3.x);
            *(float4*)&dst[outbase + (size_t)(rowg * 8 + 2 * i + 1) * DD + colg * 4] =
                make_float4(c0.y, c1.y, c2.y, c3.y);
        }
    }
}

// ---------------- k_convxdbl: fused conv+silu (-> u) + x_dbl GEMM ----------------
// l==0: xr synthesized from rank-1 x·v1+v0 (no g_xr read)
__global__ void k_convxdbl(const float* __restrict__ convW, const float* __restrict__ convb,
                           const float* __restrict__ xpW, int l,
                           const float* __restrict__ x0, const float* __restrict__ x1,
                           const float* __restrict__ x2, const float* __restrict__ x3) {
    extern __shared__ float sm[];
    float* sUt = sm;                    // [128][132]
    float* sW  = sm + 128 * 132;        // [128][38]
    float* scw = sW + 128 * 38;         // [128][4]
    float* sb  = scw + 512;             // [128]
    float* sxv = sb + 128;              // [132] (l0)
    float* sv1 = sxv + 132;             // [128] (l0)
    float* sv0 = sv1 + 128;             // [128] (l0)
    int br = blockIdx.z, b = blockIdx.y, t0 = blockIdx.x * 128;
    int tid = threadIdx.x;
    int pl = br * LL + l;
    for (int i = tid; i < 512; i += 192) scw[i] = convW[(size_t)pl * DD * KK + i];
    for (int i = tid; i < 128; i += 192) sb[i] = convb[pl * DD + i];
    if (l == 0) {
        const float* xp = (br == 0) ? x0 : (br == 1) ? x1 : (br == 2) ? x2 : x3;
        for (int i = tid; i < 131; i += 192) {
            int t = t0 - 3 + i;
            sxv[i] = (t >= 0) ? xp[b * TT + t] : 0.f;
        }
        for (int i = tid; i < 128; i += 192) {
            sv1[i] = g_v1[br * 2 * DD + i];
            sv0[i] = g_v0[br * 2 * DD + i];
        }
    }
    __syncthreads();
    size_t rowbase = (size_t)(br * BB + b) * TT;
    if (l == 0) {
        for (int i = tid; i < 16384; i += 192) {
            int r = i >> 7, d = i & 127;
            int t = t0 + r;
            float c0 = scw[d * 4 + 0], c1 = scw[d * 4 + 1];
            float c2 = scw[d * 4 + 2], c3 = scw[d * 4 + 3];
            float dot = c0 * sxv[r] + c1 * sxv[r + 1] + c2 * sxv[r + 2] + c3 * sxv[r + 3];
            float vs = c3;
            if (t >= 1) vs += c2;
            if (t >= 2) vs += c1;
            if (t >= 3) vs += c0;
            float v = sv1[d] * dot + sv0[d] * vs + sb[d];
            float uu = fsilu(v);
            g_u[(rowbase + t) * DD + d] = uu;
            sUt[d * 132 + r] = uu;
        }
    } else {
        for (int i = tid; i < 16384; i += 192) {
            int r = i >> 7, d = i & 127;
            int t = t0 + r;
            float x0v = (t >= 3) ? g_xr[(rowbase + t - 3) * DD + d] : 0.f;
            float x1v = (t >= 2) ? g_xr[(rowbase + t - 2) * DD + d] : 0.f;
            float x2v = (t >= 1) ? g_xr[(rowbase + t - 1) * DD + d] : 0.f;
            float x3v = g_xr[(rowbase + t) * DD + d];
            float v = scw[d * 4 + 0] * x0v + scw[d * 4 + 1] * x1v + scw[d * 4 + 2] * x2v
                    + scw[d * 4 + 3] * x3v + sb[d];
            float uu = fsilu(v);
            g_u[(rowbase + t) * DD + d] = uu;
            sUt[d * 132 + r] = uu;
        }
    }
    const float* Wb = xpW + (size_t)pl * 36 * DD;
    for (int i = tid; i < 4608; i += 192) {
        int e = i >> 7, k = i & 127;
        sW[k * 38 + e] = Wb[(size_t)e * DD + k];
    }
    __syncthreads();
    int rowg = tid & 31, colg = tid >> 5;
    u64 acc[4][3];
    #pragma unroll
    for (int r = 0; r < 4; r++)
        #pragma unroll
        for (int p = 0; p < 3; p++) acc[r][p] = 0ull;
    #pragma unroll 2
    for (int k = 0; k < 128; k++) {
        float4 h4 = *(const float4*)&sUt[k * 132 + rowg * 4];
        u64 w0 = *(const u64*)&sW[k * 38 + colg * 6];
        u64 w1 = *(const u64*)&sW[k * 38 + colg * 6 + 2];
        u64 w2 = *(const u64*)&sW[k * 38 + colg * 6 + 4];
        float hv[4] = {h4.x, h4.y, h4.z, h4.w};
        #pragma unroll
        for (int r = 0; r < 4; r++) {
            u64 hp = pk2(hv[r], hv[r]);
            fma2(acc[r][0], hp, w0);
            fma2(acc[r][1], hp, w1);
            fma2(acc[r][2], hp, w2);
        }
    }
    #pragma unroll
    for (int r = 0; r < 4; r++) {
        size_t ob = (rowbase + t0 + rowg * 4 + r) * 36 + colg * 6;
        #pragma unroll
        for (int p = 0; p < 3; p++) {
            float2 v = upk2(acc[r][p]);
            *(float2*)&g_xdbl[ob + 2 * p] = v;
        }
    }
}

// ---------------- k_scan1: per-chunk local scan (h_in = 0), S=sum(dt) for pfin ----------------
__global__ void __launch_bounds__(128, 8)
k_scan1(const float* __restrict__ A_log, const float* __restrict__ Dp_all,
        const float* __restrict__ dtW, const float* __restrict__ dtb, int l) {
    __shared__ float sXD[CS * 40];
    int c = blockIdx.x, bb = blockIdx.y;
    int br = bb >> 5;
    int d = threadIdx.x;
    int pl = br * LL + l;
    const float LN2 = 0.6931471805599453f;
    u64 a2[8];
    #pragma unroll
    for (int p = 0; p < 8; p++) {
        float lo = -__expf(A_log[(size_t)(pl * DD + d) * NN + 2 * p    ]) * F_LOG2E;
        float hi = -__expf(A_log[(size_t)(pl * DD + d) * NN + 2 * p + 1]) * F_LOG2E;
        a2[p] = pk2(lo, hi);
    }
    float dpv = Dp_all[pl * DD + d];
    const float* dw = dtW + (size_t)(pl * DD + d) * RR;
    float w0 = dw[0], w1 = dw[1], w2 = dw[2], w3 = dw[3];
    float db = dtb[pl * DD + d];
    u64 h2[8];
    #pragma unroll
    for (int p = 0; p < 8; p++) h2[p] = 0ull;
    float S = 0.f;
    size_t rowbase = (size_t)bb * TT + (size_t)c * CS;
    for (int i = d; i < CS * 36; i += 128) {
        int rr = i / 36, cc = i - rr * 36;
        sXD[rr * 40 + cc] = g_xdbl[rowbase * 36 + i];
    }
    __syncthreads();
    const float* up = &g_u[rowbase * DD + d];
    float* yp = &g_y[rowbase * DD + d];
    #pragma unroll 1
    for (int sg = 0; sg < CS; sg += 4) {
        float uv[4];
        #pragma unroll
        for (int q = 0; q < 4; q++) uv[q] = up[(sg + q) * DD];
        #pragma unroll
        for (int q = 0; q < 4; q++) {
            int s = sg + q;
            const float* xd = &sXD[s * 40];
            float4 x4 = *(const float4*)xd;
            float dtp = w0 * x4.x + w1 * x4.y + w2 * x4.z + w3 * x4.w + db;
            float e = ex2f(dtp * F_LOG2E);
            float dt = (dtp > 15.f) ? dtp : LN2 * lg2f(1.f + e);
            S += dt;
            float du = dt * uv[q];
            u64 du2 = pk2(du, du);
            u64 dt2 = pk2(dt, dt);
            float y = dpv * uv[q];
            u64 y2 = 0ull;
            #pragma unroll
            for (int p = 0; p < 8; p++) {
                u64 arg = mul2(dt2, a2[p]);
                float2 av = upk2(arg);
                u64 dA2 = pk2(ex2f(av.x), ex2f(av.y));
                u64 B2 = *(const u64*)&xd[4 + 2 * p];
                u64 C2 = *(const u64*)&xd[20 + 2 * p];
                u64 t2 = mul2(du2, B2);
                fma2(t2, dA2, h2[p]);
                h2[p] = t2;
                fma2(y2, t2, C2);
            }
            float2 yv = upk2(y2);
            yp[s * DD] = y + yv.x + yv.y;
        }
    }
    size_t sb = ((size_t)(bb * CH + c) * DD + d) * NN;
    u64 S2 = pk2(S, S);
    #pragma unroll
    for (int p = 0; p < 8; p++) {
        float2 hv = upk2(h2[p]);
        float2 sa = upk2(mul2(S2, a2[p]));
        *(float2*)&g_hfin[sb + 2 * p] = hv;
        *(float2*)&g_pfin[sb + 2 * p] = make_float2(ex2f(sa.x), ex2f(sa.y));
    }
}

// ---------------- k_scan2: sequential combine over chunks -> h_in per chunk ----------------
__global__ void k_scan2() {
    int idx = blockIdx.x * 256 + threadIdx.x;     // (bb*128 + d)*16 + n
    int nd = idx & (DD * NN - 1);
    int bb = idx >> 11;
    size_t base = (size_t)bb * CH * DD * NN + nd;
    float h = 0.f;
    #pragma unroll
    for (int c = 0; c < CH; c++) {
        g_hin[base + (size_t)c * DD * NN] = h;
        h = g_pfin[base + (size_t)c * DD * NN] * h + g_hfin[base + (size_t)c * DD * NN];
    }
}

// ---------------- k_scan3: y += C·(exp(S_t·a) ⊙ h_in), S_t = cumsum(softplus dt) ----------------
__global__ void __launch_bounds__(128, 8)
k_scan3(const float* __restrict__ A_log,
        const float* __restrict__ dtW, const float* __restrict__ dtb, int l) {
    __shared__ float sD[CS * 24];
    int c = blockIdx.x + 1, bb = blockIdx.y;
    int br = bb >> 5;
    int d = threadIdx.x;
    int pl = br * LL + l;
    const float LN2 = 0.6931471805599453f;
    u64 a2[8];
    #pragma unroll
    for (int p = 0; p < 8; p++) {
        float lo = -__expf(A_log[(size_t)(pl * DD + d) * NN + 2 * p    ]) * F_LOG2E;
        float hi = -__expf(A_log[(size_t)(pl * DD + d) * NN + 2 * p + 1]) * F_LOG2E;
        a2[p] = pk2(lo, hi);
    }
    const float* dw = dtW + (size_t)(pl * DD + d) * RR;
    float w0 = dw[0], w1 = dw[1], w2 = dw[2], w3 = dw[3];
    float db = dtb[pl * DD + d];
    size_t sb = ((size_t)(bb * CH + c) * DD + d) * NN;
    u64 hin2[8];
    #pragma unroll
    for (int p = 0; p < 8; p++) hin2[p] = *(const u64*)&g_hin[sb + 2 * p];
    size_t rowbase = (size_t)bb * TT + (size_t)c * CS;
    for (int i = d; i < CS * 20; i += 128) {
        int rr = i / 20, cc = i - rr * 20;
        int src = (cc < 4) ? cc : cc + 16;
        sD[rr * 24 + cc] = g_xdbl[(rowbase + rr) * 36 + src];
    }
    __syncthreads();
    float* yp = &g_y[rowbase * DD + d];
    float S = 0.f;
    #pragma unroll 1
    for (int s = 0; s < CS; s++) {
        const float* xd = &sD[s * 24];
        float4 x4 = *(const float4*)xd;
        float dtp = w0 * x4.x + w1 * x4.y + w2 * x4.z + w3 * x4.w + db;
        float e = ex2f(dtp * F_LOG2E);
        float dt = (dtp > 15.f) ? dtp : LN2 * lg2f(1.f + e);
        S += dt;
        u64 S2 = pk2(S, S);
        u64 y2 = 0ull;
        #pragma unroll
        for (int p = 0; p < 8; p++) {
            u64 arg = mul2(S2, a2[p]);
            float2 av = upk2(arg);
            u64 e2 = pk2(ex2f(av.x), ex2f(av.y));
            u64 c2 = mul2(e2, hin2[p]);
            u64 Cv = *(const u64*)&xd[4 + 2 * p];
            fma2(y2, c2, Cv);
        }
        float2 yv = upk2(y2);
        yp[s * DD] += yv.x + yv.y;
    }
}

// ---------------- k_outgemm (l==0: z synthesized from rank-1 x·v1z+v0z) ----------------
__global__ void k_outgemm(const float* __restrict__ oW, int l, int dst,
                          const float* __restrict__ x0, const float* __restrict__ x1,
                          const float* __restrict__ x2, const float* __restrict__ x3) {
    extern __shared__ float sm[];
    float* sPt = sm;                 // [128][132]
    float* sW  = sm + 128 * 132;     // [128][66]
    float* sxv = sW + 128 * 66;      // [128]  (l0)
    float* sv1z = sxv + 128;         // [128]  (l0)
    float* sv0z = sv1z + 128;        // [128]  (l0)
    int br = blockIdx.z, b = blockIdx.y, t0 = blockIdx.x * 128;
    int tid = threadIdx.x;
    size_t base = ((size_t)(br * BB + b) * TT + t0) * DD;
    if (l == 0) {
        const float* xp = (br == 0) ? x0 : (br == 1) ? x1 : (br == 2) ? x2 : x3;
        for (int i = tid; i < 128; i += 256) {
            sxv[i] = xp[b * TT + t0 + i];
            sv1z[i] = g_v1[br * 2 * DD + DD + i];
            sv0z[i] = g_v0[br * 2 * DD + DD + i];
        }
        __syncthreads();
        for (int i = tid; i < 16384; i += 256) {
            int r = i >> 7, dd = i & 127;
            float zv = sxv[r] * sv1z[dd] + sv0z[dd];
            sPt[dd * 132 + r] = g_y[base + i] * fsilu(zv) * rcpf(zv == 0.f ? 1.f : 1.f)
                              ;  // fsilu(zv) already = zv*sigmoid(zv)
        }
    } else {
        for (int i = tid; i < 16384; i += 256) {
            int r = i >> 7, dd = i & 127;
            float zv = g_z[base + i];
            sPt[dd * 132 + r] = g_y[base + i] * fsilu(zv);
        }
    }
    const float* Wb = oW + (size_t)(br * LL + l) * HH * DD;
    for (int i = tid; i < 8192; i += 256) {
        int hh = i >> 7, k = i & 127;
        sW[k * 66 + hh] = Wb[(size_t)hh * DD + k];
    }
    __syncthreads();
    int rowg = tid & 31, colg = tid >> 5;
    u64 acc[4][4];
    #pragma unroll
    for (int r = 0; r < 4; r++)
        #pragma unroll
        for (int p = 0; p < 4; p++) acc[r][p] = 0ull;
    #pragma unroll 2
    for (int k = 0; k < 128; k++) {
        float4 h4 = *(const float4*)&sPt[k * 132 + rowg * 4];
        u64 w0 = *(const u64*)&sW[k * 66 + colg * 8];
        u64 w1 = *(const u64*)&sW[k * 66 + colg * 8 + 2];
        u64 w2 = *(const u64*)&sW[k * 66 + colg * 8 + 4];
        u64 w3 = *(const u64*)&sW[k * 66 + colg * 8 + 6];
        float hv[4] = {h4.x, h4.y, h4.z, h4.w};
        #pragma unroll
        for (int r = 0; r < 4; r++) {
            u64 hp = pk2(hv[r], hv[r]);
            fma2(acc[r][0], hp, w0);
            fma2(acc[r][1], hp, w1);
            fma2(acc[r][2], hp, w2);
            fma2(acc[r][3], hp, w3);
        }
    }
    float* hb = g_h[dst] + ((size_t)(br * BB + b) * TT + t0) * HH;
    #pragma unroll
    for (int r = 0; r < 4; r++) {
        int row = rowg * 4 + r;
        float2 p0 = upk2(acc[r][0]), p1 = upk2(acc[r][1]);
        float2 p2 = upk2(acc[r][2]), p3 = upk2(acc[r][3]);
        *(float4*)&hb[(size_t)row * HH + colg * 8]     = make_float4(p0.x, p0.y, p1.x, p1.y);
        *(float4*)&hb[(size_t)row * HH + colg * 8 + 4] = make_float4(p2.x, p2.y, p3.x, p3.y);
    }
}

// ---------------- k_head ----------------
__global__ void k_head(const float* __restrict__ opW, const float* __restrict__ opb,
                       float* __restrict__ out, int src) {
    __shared__ float sH[64 * 64];
    __shared__ float sW[64 * 33];
    __shared__ float sB[32];
    int br = blockIdx.z, b = blockIdx.y, t0 = blockIdx.x * 64;
    int tid = threadIdx.x;
    const float* hb = g_h[src] + ((size_t)(br * BB + b) * TT + t0) * HH;
    for (int i = tid; i < 4096; i += 256) sH[i] = hb[i];
    for (int i = tid; i < 2048; i += 256) {
        int e = i >> 6, hh = i & 63;
        sW[hh * 33 + e] = opW[(size_t)br * EE * HH + i];
    }
    if (tid < 32) sB[tid] = opb[br * EE + tid];
    __syncthreads();
    int e = tid & 31, rg = tid >> 5;
    #pragma unroll
    for (int i = 0; i < 8; i++) {
        int r = rg * 8 + i;
        float acc = sB[e];
        #pragma unroll
        for (int hh = 0; hh < 64; hh++) acc += sH[r * 64 + hh] * sW[hh * 33 + e];
        float z = ftanh(acc);
        float n2 = wsum(z * z);
        float n = sqrtf(fmaxf(n2, 1e-15f));
        float zh = z * ftanh(n) * rcpf(n);
        float n2b = wsum(zh * zh);
        float nb = sqrtf(fmaxf(n2b, 1e-15f));
        if (nb > MAXN) zh *= MAXN * rcpf(nb);
        out[(size_t)br * BB * TT * EE + ((size_t)(b * TT + t0 + r)) * EE + e] = zh;
    }
}

// ---------------- k_mobius ----------------
__device__ __forceinline__ float mob(float x, float y) {
    float x2 = wsum(x * x);
    float y2 = wsum(y * y);
    float xy = wsum(x * y);
    float num = (1.f + 2.f * xy + y2) * x + (1.f - x2) * y;
    float den = 1.f + 2.f * xy + x2 * y2;
    return num * rcpf(fmaxf(den, 1e-15f));
}

__global__ void k_mobius(float* __restrict__ out) {
    int warp = threadIdx.x >> 5, e = threadIdx.x & 31;
    size_t row = (size_t)blockIdx.x * 8 + warp;
    size_t S = (size_t)BB * TT * EE;
    float tv = out[0 * S + row * EE + e];
    float wv = out[1 * S + row * EE + e];
    float dv = out[2 * S + row * EE + e];
    float rv = out[3 * S + row * EE + e];
    float m = mob(wv, dv);
    m = mob(tv, m);
    m = mob(m, rv);
    float n2 = wsum(m * m);
    float n = sqrtf(fmaxf(n2, 1e-15f));
    if (n > MAXN) m *= MAXN * rcpf(n);
    out[4 * S + row * EE + e] = m;
}

// ---------------- launch ----------------
extern "C" void kernel_launch(void* const* d_in, const int* in_sizes, int n_in,
                              void* d_out, int out_size) {
    const float* trend = (const float*)d_in[0];
    const float* sweek = (const float*)d_in[1];
    const float* sday  = (const float*)d_in[2];
    const float* resid = (const float*)d_in[3];
    const float* inp_W = (const float*)d_in[4];
    const float* inp_b = (const float*)d_in[5];
    const float* in_proj_W = (const float*)d_in[6];
    const float* conv_W = (const float*)d_in[7];
    const float* conv_b = (const float*)d_in[8];
    const float* xproj_W = (const float*)d_in[9];
    const float* dt_W = (const float*)d_in[10];
    const float* dt_b = (const float*)d_in[11];
    const float* A_log = (const float*)d_in[12];
    const float* D_skip = (const float*)d_in[13];
    const float* out_W = (const float*)d_in[14];
    const float* outp_W = (const float*)d_in[15];
    const float* outp_b = (const float*)d_in[16];
    float* out = (float*)d_out;

    const int SM_INPROJ = (64 * 68 + 64 * 132) * 4;
    const int SM_CONVXD = (128 * 132 + 128 * 38 + 512 + 128 + 132 + 256) * 4;
    const int SM_OUTG   = (128 * 132 + 128 * 66 + 384) * 4;
    cudaFuncSetAttribute(k_inproj,   cudaFuncAttributeMaxDynamicSharedMemorySize, SM_INPROJ);
    cudaFuncSetAttribute(k_convxdbl, cudaFuncAttributeMaxDynamicSharedMemorySize, SM_CONVXD);
    cudaFuncSetAttribute(k_outgemm,  cudaFuncAttributeMaxDynamicSharedMemorySize, SM_OUTG);

    k_prep0<<<BR, 256>>>(in_proj_W, inp_W, inp_b);

    for (int l = 0; l < LL; l++) {
        int src = l & 1, dst = (l + 1) & 1;
        if (l > 0)
            k_inproj<<<dim3(16, 32, 4), 256, SM_INPROJ>>>(in_proj_W, l, src);
        k_convxdbl<<<dim3(8, 32, 4), 192, SM_CONVXD>>>(conv_W, conv_b, xproj_W, l,
                                                       trend, sweek, sday, resid);
        k_scan1<<<dim3(CH, BR * BB), 128>>>(A_log, D_skip, dt_W, dt_b, l);
        k_scan2<<<(BR * BB * DD * NN) / 256, 256>>>();
        k_scan3<<<dim3(CH - 1, BR * BB), 128>>>(A_log, dt_W, dt_b, l);
        k_outgemm<<<dim3(8, 32, 4), 256, SM_OUTG>>>(out_W, l, dst,
                                                    trend, sweek, sday, resid);
    }

    k_head<<<dim3(16, 32, 4), 256>>>(outp_W, outp_b, out, LL & 1);
    k_mobius<<<(BB * TT) / 8, 256>>>(out);
}

// round 15
// speedup vs baseline: 1.2465x; 1.2465x over previous
#include <cuda_runtime.h>
#include <cuda_bf16.h>
#include <math.h>

#define BR 4
#define BB 32
#define TT 1024
#define HH 64
#define DD 128
#define NN 16
#define KK 4
#define RR 4
#define EE 32
#define LL 3
#define CH 16          // scan chunks
#define CS 64          // steps per chunk
#define MAXN 0.996f

typedef unsigned long long u64;

// ---------------- f32x2 packed-FMA helpers (sm_103a FFMA2 path) ----------------
__device__ __forceinline__ u64 pk2(float x, float y) {
    u64 r; asm("mov.b64 %0, {%1, %2};" : "=l"(r) : "f"(x), "f"(y)); return r;
}
__device__ __forceinline__ float2 upk2(u64 v) {
    float2 r; asm("mov.b64 {%0, %1}, %2;" : "=f"(r.x), "=f"(r.y) : "l"(v)); return r;
}
__device__ __forceinline__ void fma2(u64& d, u64 a, u64 b) {
    asm("fma.rn.f32x2 %0, %1, %2, %0;" : "+l"(d) : "l"(a), "l"(b));
}
__device__ __forceinline__ u64 mul2(u64 a, u64 b) {
    u64 r; asm("mul.rn.f32x2 %0, %1, %2;" : "=l"(r) : "l"(a), "l"(b)); return r;
}
__device__ __forceinline__ float ex2f(float x) {
    float r; asm("ex2.approx.f32 %0, %1;" : "=f"(r) : "f"(x)); return r;
}
__device__ __forceinline__ float lg2f(float x) {
    float r; asm("lg2.approx.f32 %0, %1;" : "=f"(r) : "f"(x)); return r;
}
__device__ __forceinline__ float rcpf(float x) {
    float r; asm("rcp.approx.f32 %0, %1;" : "=f"(r) : "f"(x)); return r;
}
#define F_LOG2E 1.4426950408889634f
__device__ __forceinline__ float fsilu(float v) {
    return v * rcpf(1.f + ex2f(-v * F_LOG2E));
}
__device__ __forceinline__ float ftanh(float x) {
    return 1.f - 2.f * rcpf(ex2f(2.f * F_LOG2E * x) + 1.f);
}

union F4U {
    float4 f;
    struct { u64 lo, hi; } d;
};

// ---------------- scratch (device globals; no allocation allowed) ----------------
__device__ float g_h[2][(size_t)BR*BB*TT*HH];
__device__ float g_xr[(size_t)BR*BB*TT*DD];
__device__ float g_z [(size_t)BR*BB*TT*DD];
__device__ float g_u [(size_t)BR*BB*TT*DD];
__device__ float g_xdbl[(size_t)BR*BB*TT*36];
__device__ float g_y [(size_t)BR*BB*TT*DD];
// chunked-scan carries: [bb][chunk][d][n]
__device__ float g_hfin[(size_t)BR*BB*CH*DD*NN];
__device__ float g_pfin[(size_t)BR*BB*CH*DD*NN];
__device__ float g_hin [(size_t)BR*BB*CH*DD*NN];
// rank-1 layer-0 folded weights
__device__ float g_v1[BR * 2 * DD];
__device__ float g_v0[BR * 2 * DD];

__device__ __forceinline__ float wsum(float v) {
    #pragma unroll
    for (int o = 16; o; o >>= 1) v += __shfl_xor_sync(0xffffffffu, v, o);
    return v;
}

// ---------------- k_prep0: fold embed into layer-0 in_proj (rank-1) ----------------
__global__ void k_prep0(const float* __restrict__ inW_all,
                        const float* __restrict__ iW, const float* __restrict__ ib) {
    int br = blockIdx.x, dd = threadIdx.x;
    const float* Wb = inW_all + ((size_t)(br * LL) * 2 * DD + dd) * HH;
    const float* iwp = iW + br * HH;
    const float* ibp = ib + br * HH;
    float v1 = 0.f, v0 = 0.f;
    #pragma unroll
    for (int h = 0; h < HH; h++) {
        float w = Wb[h];
        v1 += iwp[h] * w;
        v0 += ibp[h] * w;
    }
    g_v1[br * 2 * DD + dd] = v1;
    g_v0[br * 2 * DD + dd] = v0;
}

// ---------------- k_inproj: row-packed FFMA2 (layers 1,2) ----------------
__global__ void k_inproj(const float* __restrict__ inW_all, int l, int src) {
    extern __shared__ float sm[];
    float* sHt = sm;              // [64][68] transposed
    float* sW  = sm + 64 * 68;    // [64][132]
    int br = blockIdx.z, b = blockIdx.y, t0 = blockIdx.x * 64;
    int tid = threadIdx.x;
    const float* Wb = inW_all + (size_t)((br * LL + l) * 2 * DD) * HH;
    const float* hb = g_h[src] + ((size_t)(br * BB + b) * TT + t0) * HH;
    // transposed fill: 4 rows per item, STS.128 (row stride 68 floats = 272B, 16B-aligned)
    for (int i = tid; i < 1024; i += 256) {
        int k = i & 63, rg = i >> 6;
        float h0 = hb[(size_t)(rg * 4 + 0) * HH + k];
        float h1 = hb[(size_t)(rg * 4 + 1) * HH + k];
        float h2 = hb[(size_t)(rg * 4 + 2) * HH + k];
        float h3 = hb[(size_t)(rg * 4 + 3) * HH + k];
        *(float4*)&sHt[k * 68 + rg * 4] = make_float4(h0, h1, h2, h3);
    }

    size_t outbase = ((size_t)(br * BB + b) * TT + t0) * DD;
    int rowg = tid & 7, colg = tid >> 3;
    for (int dc = 0; dc < 2; dc++) {
        __syncthreads();
        int d0 = dc * 128;
        for (int i = tid; i < 2048; i += 256) {
            int k = i & 63, dg = i >> 6;
            float w0 = Wb[(size_t)(d0 + dg * 4 + 0) * HH + k];
            float w1 = Wb[(size_t)(d0 + dg * 4 + 1) * HH + k];
            float w2 = Wb[(size_t)(d0 + dg * 4 + 2) * HH + k];
            float w3 = Wb[(size_t)(d0 + dg * 4 + 3) * HH + k];
            *(float4*)&sW[k * 132 + dg * 4] = make_float4(w0, w1, w2, w3);
        }
        __syncthreads();
        u64 acc[4][4];
        #pragma unroll
        for (int i = 0; i < 4; i++)
            #pragma unroll
            for (int j = 0; j < 4; j++) acc[i][j] = 0ull;
        #pragma unroll 4
        for (int k = 0; k < 64; k++) {
            F4U hA, hB;
            hA.f = *(const float4*)&sHt[k * 68 + rowg * 8];
            hB.f = *(const float4*)&sHt[k * 68 + rowg * 8 + 4];
            u64 rp[4] = {hA.d.lo, hA.d.hi, hB.d.lo, hB.d.hi};
            float4 w = *(const float4*)&sW[k * 132 + colg * 4];
            u64 wb[4] = {pk2(w.x, w.x), pk2(w.y, w.y), pk2(w.z, w.z), pk2(w.w, w.w)};
            #pragma unroll
            for (int i = 0; i < 4; i++)
                #pragma unroll
                for (int j = 0; j < 4; j++)
                    fma2(acc[i][j], rp[i], wb[j]);
        }
        float* dst = (dc == 0) ? g_xr : g_z;
        #pragma unroll
        for (int i = 0; i < 4; i++) {
            float2 c0 = upk2(acc[i][0]), c1 = upk2(acc[i][1]);
            float2 c2 = upk2(acc[i][2]), c3 = upk2(acc[i][3]);
            *(float4*)&dst[outbase + (size_t)(rowg * 8 + 2 * i) * DD + colg * 4] =
                make_float4(c0.x, c1.x, c2.x, c3.x);
            *(float4*)&dst[outbase + (size_t)(rowg * 8 + 2 * i + 1) * DD + colg * 4] =
                make_float4(c0.y, c1.y, c2.y, c3.y);
        }
    }
}

// ---------------- k_convxdbl: fused conv+silu (-> u) + x_dbl GEMM ----------------
// conv path: 4 rows per thread at one d -> 7 LDG / 4 outputs, conflict-free STS.128
__global__ void k_convxdbl(const float* __restrict__ convW, const float* __restrict__ convb,
                           const float* __restrict__ xpW, int l,
                           const float* __restrict__ x0, const float* __restrict__ x1,
                           const float* __restrict__ x2, const float* __restrict__ x3) {
    extern __shared__ float sm[];
    float* sUt = sm;                    // [128][132]
    float* sW  = sm + 128 * 132;        // [128][38]
    float* scw = sW + 128 * 38;         // [128][4]
    float* sb  = scw + 512;             // [128]
    float* sxv = sb + 128;              // [132] (l0)
    float* sv1 = sxv + 132;             // [128] (l0)
    float* sv0 = sv1 + 128;             // [128] (l0)
    int br = blockIdx.z, b = blockIdx.y, t0 = blockIdx.x * 128;
    int tid = threadIdx.x;
    int pl = br * LL + l;
    for (int i = tid; i < 512; i += 192) scw[i] = convW[(size_t)pl * DD * KK + i];
    for (int i = tid; i < 128; i += 192) sb[i] = convb[pl * DD + i];
    if (l == 0) {
        const float* xp = (br == 0) ? x0 : (br == 1) ? x1 : (br == 2) ? x2 : x3;
        for (int i = tid; i < 131; i += 192) {
            int t = t0 - 3 + i;
            sxv[i] = (t >= 0) ? xp[b * TT + t] : 0.f;
        }
        for (int i = tid; i < 128; i += 192) {
            sv1[i] = g_v1[br * 2 * DD + i];
            sv0[i] = g_v0[br * 2 * DD + i];
        }
    }
    __syncthreads();
    size_t rowbase = (size_t)(br * BB + b) * TT;
    if (l == 0) {
        for (int i = tid; i < 4096; i += 192) {
            int rg = i >> 7, d = i & 127;
            float c0 = scw[d * 4 + 0], c1 = scw[d * 4 + 1];
            float c2 = scw[d * 4 + 2], c3 = scw[d * 4 + 3];
            float bias = sb[d];
            float sv1d = sv1[d], sv0d = sv0[d];
            float uu[4];
            size_t gbase = (rowbase + t0 + rg * 4) * DD + d;
            #pragma unroll
            for (int j = 0; j < 4; j++) {
                int r = rg * 4 + j;
                int t = t0 + r;
                float dot = c0 * sxv[r] + c1 * sxv[r + 1] + c2 * sxv[r + 2] + c3 * sxv[r + 3];
                float vs = c3;
                if (t >= 1) vs += c2;
                if (t >= 2) vs += c1;
                if (t >= 3) vs += c0;
                float v = sv1d * dot + sv0d * vs + bias;
                uu[j] = fsilu(v);
                g_u[gbase + (size_t)j * DD] = uu[j];
            }
            *(float4*)&sUt[d * 132 + rg * 4] = make_float4(uu[0], uu[1], uu[2], uu[3]);
        }
    } else {
        for (int i = tid; i < 4096; i += 192) {
            int rg = i >> 7, d = i & 127;
            int tb = t0 + rg * 4;
            float xw[7];
            #pragma unroll
            for (int j = 0; j < 7; j++) {
                int t = tb - 3 + j;
                xw[j] = (t >= 0) ? g_xr[(rowbase + t) * DD + d] : 0.f;
            }
            float c0 = scw[d * 4 + 0], c1 = scw[d * 4 + 1];
            float c2 = scw[d * 4 + 2], c3 = scw[d * 4 + 3];
            float bias = sb[d];
            float uu[4];
            size_t gbase = (rowbase + tb) * DD + d;
            #pragma unroll
            for (int j = 0; j < 4; j++) {
                float v = c0 * xw[j] + c1 * xw[j + 1] + c2 * xw[j + 2] + c3 * xw[j + 3] + bias;
                uu[j] = fsilu(v);
                g_u[gbase + (size_t)j * DD] = uu[j];
            }
            *(float4*)&sUt[d * 132 + rg * 4] = make_float4(uu[0], uu[1], uu[2], uu[3]);
        }
    }
    const float* Wb = xpW + (size_t)pl * 36 * DD;
    for (int i = tid; i < 4608; i += 192) {
        int e = i >> 7, k = i & 127;
        sW[k * 38 + e] = Wb[(size_t)e * DD + k];
    }
    __syncthreads();
    int rowg = tid & 31, colg = tid >> 5;
    u64 acc[4][3];
    #pragma unroll
    for (int r = 0; r < 4; r++)
        #pragma unroll
        for (int p = 0; p < 3; p++) acc[r][p] = 0ull;
    #pragma unroll 2
    for (int k = 0; k < 128; k++) {
        float4 h4 = *(const float4*)&sUt[k * 132 + rowg * 4];
        u64 w0 = *(const u64*)&sW[k * 38 + colg * 6];
        u64 w1 = *(const u64*)&sW[k * 38 + colg * 6 + 2];
        u64 w2 = *(const u64*)&sW[k * 38 + colg * 6 + 4];
        float hv[4] = {h4.x, h4.y, h4.z, h4.w};
        #pragma unroll
        for (int r = 0; r < 4; r++) {
            u64 hp = pk2(hv[r], hv[r]);
            fma2(acc[r][0], hp, w0);
            fma2(acc[r][1], hp, w1);
            fma2(acc[r][2], hp, w2);
        }
    }
    #pragma unroll
    for (int r = 0; r < 4; r++) {
        size_t ob = (rowbase + t0 + rowg * 4 + r) * 36 + colg * 6;
        #pragma unroll
        for (int p = 0; p < 3; p++) {
            float2 v = upk2(acc[r][p]);
            *(float2*)&g_xdbl[ob + 2 * p] = v;
        }
    }
}

// ---------------- k_scan1: per-chunk local scan (h_in = 0), S=sum(dt) for pfin ----------------
__global__ void __launch_bounds__(128, 8)
k_scan1(const float* __restrict__ A_log, const float* __restrict__ Dp_all,
        const float* __restrict__ dtW, const float* __restrict__ dtb, int l) {
    __shared__ float sXD[CS * 40];
    int c = blockIdx.x, bb = blockIdx.y;
    int br = bb >> 5;
    int d = threadIdx.x;
    int pl = br * LL + l;
    const float LN2 = 0.6931471805599453f;
    u64 a2[8];
    #pragma unroll
    for (int p = 0; p < 8; p++) {
        float lo = -__expf(A_log[(size_t)(pl * DD + d) * NN + 2 * p    ]) * F_LOG2E;
        float hi = -__expf(A_log[(size_t)(pl * DD + d) * NN + 2 * p + 1]) * F_LOG2E;
        a2[p] = pk2(lo, hi);
    }
    float dpv = Dp_all[pl * DD + d];
    const float* dw = dtW + (size_t)(pl * DD + d) * RR;
    float w0 = dw[0], w1 = dw[1], w2 = dw[2], w3 = dw[3];
    float db = dtb[pl * DD + d];
    u64 h2[8];
    #pragma unroll
    for (int p = 0; p < 8; p++) h2[p] = 0ull;
    float S = 0.f;
    size_t rowbase = (size_t)bb * TT + (size_t)c * CS;
    for (int i = d; i < CS * 36; i += 128) {
        int rr = i / 36, cc = i - rr * 36;
        sXD[rr * 40 + cc] = g_xdbl[rowbase * 36 + i];
    }
    __syncthreads();
    const float* up = &g_u[rowbase * DD + d];
    float* yp = &g_y[rowbase * DD + d];
    #pragma unroll 1
    for (int sg = 0; sg < CS; sg += 4) {
        float uv[4];
        #pragma unroll
        for (int q = 0; q < 4; q++) uv[q] = up[(sg + q) * DD];
        #pragma unroll
        for (int q = 0; q < 4; q++) {
            int s = sg + q;
            const float* xd = &sXD[s * 40];
            float4 x4 = *(const float4*)xd;
            float dtp = w0 * x4.x + w1 * x4.y + w2 * x4.z + w3 * x4.w + db;
            float e = ex2f(dtp * F_LOG2E);
            float dt = (dtp > 15.f) ? dtp : LN2 * lg2f(1.f + e);
            S += dt;
            float du = dt * uv[q];
            u64 du2 = pk2(du, du);
            u64 dt2 = pk2(dt, dt);
            float y = dpv * uv[q];
            u64 y2 = 0ull;
            #pragma unroll
            for (int p = 0; p < 8; p++) {
                u64 arg = mul2(dt2, a2[p]);
                float2 av = upk2(arg);
                u64 dA2 = pk2(ex2f(av.x), ex2f(av.y));
                u64 B2 = *(const u64*)&xd[4 + 2 * p];
                u64 C2 = *(const u64*)&xd[20 + 2 * p];
                u64 t2 = mul2(du2, B2);
                fma2(t2, dA2, h2[p]);
                h2[p] = t2;
                fma2(y2, t2, C2);
            }
            float2 yv = upk2(y2);
            yp[s * DD] = y + yv.x + yv.y;
        }
    }
    size_t sb = ((size_t)(bb * CH + c) * DD + d) * NN;
    u64 S2 = pk2(S, S);
    #pragma unroll
    for (int p = 0; p < 8; p++) {
        float2 hv = upk2(h2[p]);
        float2 sa = upk2(mul2(S2, a2[p]));
        *(float2*)&g_hfin[sb + 2 * p] = hv;
        *(float2*)&g_pfin[sb + 2 * p] = make_float2(ex2f(sa.x), ex2f(sa.y));
    }
}

// ---------------- k_scan2: sequential combine over chunks -> h_in per chunk ----------------
__global__ void k_scan2() {
    int idx = blockIdx.x * 256 + threadIdx.x;     // (bb*128 + d)*16 + n
    int nd = idx & (DD * NN - 1);
    int bb = idx >> 11;
    size_t base = (size_t)bb * CH * DD * NN + nd;
    float h = 0.f;
    #pragma unroll
    for (int c = 0; c < CH; c++) {
        g_hin[base + (size_t)c * DD * NN] = h;
        h = g_pfin[base + (size_t)c * DD * NN] * h + g_hfin[base + (size_t)c * DD * NN];
    }
}

// ---------------- k_scan3: y += C·(exp(S_t·a) ⊙ h_in), S_t = cumsum(softplus dt) ----------------
__global__ void __launch_bounds__(128, 8)
k_scan3(const float* __restrict__ A_log,
        const float* __restrict__ dtW, const float* __restrict__ dtb, int l) {
    __shared__ float sD[CS * 24];
    int c = blockIdx.x + 1, bb = blockIdx.y;
    int br = bb >> 5;
    int d = threadIdx.x;
    int pl = br * LL + l;
    const float LN2 = 0.6931471805599453f;
    u64 a2[8];
    #pragma unroll
    for (int p = 0; p < 8; p++) {
        float lo = -__expf(A_log[(size_t)(pl * DD + d) * NN + 2 * p    ]) * F_LOG2E;
        float hi = -__expf(A_log[(size_t)(pl * DD + d) * NN + 2 * p + 1]) * F_LOG2E;
        a2[p] = pk2(lo, hi);
    }
    const float* dw = dtW + (size_t)(pl * DD + d) * RR;
    float w0 = dw[0], w1 = dw[1], w2 = dw[2], w3 = dw[3];
    float db = dtb[pl * DD + d];
    size_t sb = ((size_t)(bb * CH + c) * DD + d) * NN;
    u64 hin2[8];
    #pragma unroll
    for (int p = 0; p < 8; p++) hin2[p] = *(const u64*)&g_hin[sb + 2 * p];
    size_t rowbase = (size_t)bb * TT + (size_t)c * CS;
    for (int i = d; i < CS * 20; i += 128) {
        int rr = i / 20, cc = i - rr * 20;
        int src = (cc < 4) ? cc : cc + 16;
        sD[rr * 24 + cc] = g_xdbl[(rowbase + rr) * 36 + src];
    }
    __syncthreads();
    float* yp = &g_y[rowbase * DD + d];
    float S = 0.f;
    #pragma unroll 1
    for (int s = 0; s < CS; s++) {
        const float* xd = &sD[s * 24];
        float4 x4 = *(const float4*)xd;
        float dtp = w0 * x4.x + w1 * x4.y + w2 * x4.z + w3 * x4.w + db;
        float e = ex2f(dtp * F_LOG2E);
        float dt = (dtp > 15.f) ? dtp : LN2 * lg2f(1.f + e);
        S += dt;
        u64 S2 = pk2(S, S);
        u64 y2 = 0ull;
        #pragma unroll
        for (int p = 0; p < 8; p++) {
            u64 arg = mul2(S2, a2[p]);
            float2 av = upk2(arg);
            u64 e2 = pk2(ex2f(av.x), ex2f(av.y));
            u64 c2 = mul2(e2, hin2[p]);
            u64 Cv = *(const u64*)&xd[4 + 2 * p];
            fma2(y2, c2, Cv);
        }
        float2 yv = upk2(y2);
        yp[s * DD] += yv.x + yv.y;
    }
}

// ---------------- k_outgemm (l==0: z synthesized from rank-1 x·v1z+v0z) ----------------
// weight tile row padded to 68 floats (272B) so STS.128 stays 16B-aligned for all k
__global__ void k_outgemm(const float* __restrict__ oW, int l, int dst,
                          const float* __restrict__ x0, const float* __restrict__ x1,
                          const float* __restrict__ x2, const float* __restrict__ x3) {
    extern __shared__ float sm[];
    float* sPt = sm;                 // [128][132]
    float* sW  = sm + 128 * 132;     // [128][68]
    float* sxv = sW + 128 * 68;      // [128]  (l0)
    float* sv1z = sxv + 128;         // [128]  (l0)
    float* sv0z = sv1z + 128;        // [128]  (l0)
    int br = blockIdx.z, b = blockIdx.y, t0 = blockIdx.x * 128;
    int tid = threadIdx.x;
    size_t base = ((size_t)(br * BB + b) * TT + t0) * DD;
    if (l == 0) {
        const float* xp = (br == 0) ? x0 : (br == 1) ? x1 : (br == 2) ? x2 : x3;
        for (int i = tid; i < 128; i += 256) {
            sxv[i] = xp[b * TT + t0 + i];
            sv1z[i] = g_v1[br * 2 * DD + DD + i];
            sv0z[i] = g_v0[br * 2 * DD + DD + i];
        }
        __syncthreads();
        for (int i = tid; i < 4096; i += 256) {
            int rg = i >> 7, dd = i & 127;
            size_t gb = base + (size_t)(rg * 4) * DD + dd;
            float v1z = sv1z[dd], v0z = sv0z[dd];
            float p[4];
            #pragma unroll
            for (int j = 0; j < 4; j++) {
                float zv = sxv[rg * 4 + j] * v1z + v0z;
                p[j] = g_y[gb + (size_t)j * DD] * fsilu(zv);
            }
            *(float4*)&sPt[dd * 132 + rg * 4] = make_float4(p[0], p[1], p[2], p[3]);
        }
    } else {
        for (int i = tid; i < 4096; i += 256) {
            int rg = i >> 7, dd = i & 127;
            size_t gb = base + (size_t)(rg * 4) * DD + dd;
            float p[4];
            #pragma unroll
            for (int j = 0; j < 4; j++) {
                float zv = g_z[gb + (size_t)j * DD];
                p[j] = g_y[gb + (size_t)j * DD] * fsilu(zv);
            }
            *(float4*)&sPt[dd * 132 + rg * 4] = make_float4(p[0], p[1], p[2], p[3]);
        }
    }
    const float* Wb = oW + (size_t)(br * LL + l) * HH * DD;
    for (int i = tid; i < 2048; i += 256) {
        int k = i & 127, hg = i >> 7;
        float w0 = Wb[(size_t)(hg * 4 + 0) * DD + k];
        float w1 = Wb[(size_t)(hg * 4 + 1) * DD + k];
        float w2 = Wb[(size_t)(hg * 4 + 2) * DD + k];
        float w3 = Wb[(size_t)(hg * 4 + 3) * DD + k];
        *(float4*)&sW[k * 68 + hg * 4] = make_float4(w0, w1, w2, w3);
    }
    __syncthreads();
    int rowg = tid & 31, colg = tid >> 5;
    u64 acc[4][4];
    #pragma unroll
    for (int r = 0; r < 4; r++)
        #pragma unroll
        for (int p = 0; p < 4; p++) acc[r][p] = 0ull;
    #pragma unroll 2
    for (int k = 0; k < 128; k++) {
        float4 h4 = *(const float4*)&sPt[k * 132 + rowg * 4];
        u64 w0 = *(const u64*)&sW[k * 68 + colg * 8];
        u64 w1 = *(const u64*)&sW[k * 68 + colg * 8 + 2];
        u64 w2 = *(const u64*)&sW[k * 68 + colg * 8 + 4];
        u64 w3 = *(const u64*)&sW[k * 68 + colg * 8 + 6];
        float hv[4] = {h4.x, h4.y, h4.z, h4.w};
        #pragma unroll
        for (int r = 0; r < 4; r++) {
            u64 hp = pk2(hv[r], hv[r]);
            fma2(acc[r][0], hp, w0);
            fma2(acc[r][1], hp, w1);
            fma2(acc[r][2], hp, w2);
            fma2(acc[r][3], hp, w3);
        }
    }
    float* hb = g_h[dst] + ((size_t)(br * BB + b) * TT + t0) * HH;
    #pragma unroll
    for (int r = 0; r < 4; r++) {
        int row = rowg * 4 + r;
        float2 p0 = upk2(acc[r][0]), p1 = upk2(acc[r][1]);
        float2 p2 = upk2(acc[r][2]), p3 = upk2(acc[r][3]);
        *(float4*)&hb[(size_t)row * HH + colg * 8]     = make_float4(p0.x, p0.y, p1.x, p1.y);
        *(float4*)&hb[(size_t)row * HH + colg * 8 + 4] = make_float4(p2.x, p2.y, p3.x, p3.y);
    }
}

// ---------------- k_head ----------------
__global__ void k_head(const float* __restrict__ opW, const float* __restrict__ opb,
                       float* __restrict__ out, int src) {
    __shared__ float sH[64 * 64];
    __shared__ float sW[64 * 33];
    __shared__ float sB[32];
    int br = blockIdx.z, b = blockIdx.y, t0 = blockIdx.x * 64;
    int tid = threadIdx.x;
    const float* hb = g_h[src] + ((size_t)(br * BB + b) * TT + t0) * HH;
    for (int i = tid; i < 4096; i += 256) sH[i] = hb[i];
    for (int i = tid; i < 2048; i += 256) {
        int e = i >> 6, hh = i & 63;
        sW[hh * 33 + e] = opW[(size_t)br * EE * HH + i];
    }
    if (tid < 32) sB[tid] = opb[br * EE + tid];
    __syncthreads();
    int e = tid & 31, rg = tid >> 5;
    #pragma unroll
    for (int i = 0; i < 8; i++) {
        int r = rg * 8 + i;
        float acc = sB[e];
        #pragma unroll
        for (int hh = 0; hh < 64; hh++) acc += sH[r * 64 + hh] * sW[hh * 33 + e];
        float z = ftanh(acc);
        float n2 = wsum(z * z);
        float n = sqrtf(fmaxf(n2, 1e-15f));
        float zh = z * ftanh(n) * rcpf(n);
        float n2b = wsum(zh * zh);
        float nb = sqrtf(fmaxf(n2b, 1e-15f));
        if (nb > MAXN) zh *= MAXN * rcpf(nb);
        out[(size_t)br * BB * TT * EE + ((size_t)(b * TT + t0 + r)) * EE + e] = zh;
    }
}

// ---------------- k_mobius ----------------
__device__ __forceinline__ float mob(float x, float y) {
    float x2 = wsum(x * x);
    float y2 = wsum(y * y);
    float xy = wsum(x * y);
    float num = (1.f + 2.f * xy + y2) * x + (1.f - x2) * y;
    float den = 1.f + 2.f * xy + x2 * y2;
    return num * rcpf(fmaxf(den, 1e-15f));
}

__global__ void k_mobius(float* __restrict__ out) {
    int warp = threadIdx.x >> 5, e = threadIdx.x & 31;
    size_t row = (size_t)blockIdx.x * 8 + warp;
    size_t S = (size_t)BB * TT * EE;
    float tv = out[0 * S + row * EE + e];
    float wv = out[1 * S + row * EE + e];
    float dv = out[2 * S + row * EE + e];
    float rv = out[3 * S + row * EE + e];
    float m = mob(wv, dv);
    m = mob(tv, m);
    m = mob(m, rv);
    float n2 = wsum(m * m);
    float n = sqrtf(fmaxf(n2, 1e-15f));
    if (n > MAXN) m *= MAXN * rcpf(n);
    out[4 * S + row * EE + e] = m;
}

// ---------------- launch ----------------
extern "C" void kernel_launch(void* const* d_in, const int* in_sizes, int n_in,
                              void* d_out, int out_size) {
    const float* trend = (const float*)d_in[0];
    const float* sweek = (const float*)d_in[1];
    const float* sday  = (const float*)d_in[2];
    const float* resid = (const float*)d_in[3];
    const float* inp_W = (const float*)d_in[4];
    const float* inp_b = (const float*)d_in[5];
    const float* in_proj_W = (const float*)d_in[6];
    const float* conv_W = (const float*)d_in[7];
    const float* conv_b = (const float*)d_in[8];
    const float* xproj_W = (const float*)d_in[9];
    const float* dt_W = (const float*)d_in[10];
    const float* dt_b = (const float*)d_in[11];
    const float* A_log = (const float*)d_in[12];
    const float* D_skip = (const float*)d_in[13];
    const float* out_W = (const float*)d_in[14];
    const float* outp_W = (const float*)d_in[15];
    const float* outp_b = (const float*)d_in[16];
    float* out = (float*)d_out;

    const int SM_INPROJ = (64 * 68 + 64 * 132) * 4;
    const int SM_CONVXD = (128 * 132 + 128 * 38 + 512 + 128 + 132 + 256) * 4;
    const int SM_OUTG   = (128 * 132 + 128 * 68 + 384) * 4;
    cudaFuncSetAttribute(k_inproj,   cudaFuncAttributeMaxDynamicSharedMemorySize, SM_INPROJ);
    cudaFuncSetAttribute(k_convxdbl, cudaFuncAttributeMaxDynamicSharedMemorySize, SM_CONVXD);
    cudaFuncSetAttribute(k_outgemm,  cudaFuncAttributeMaxDynamicSharedMemorySize, SM_OUTG);

    k_prep0<<<BR, 256>>>(in_proj_W, inp_W, inp_b);

    for (int l = 0; l < LL; l++) {
        int src = l & 1, dst = (l + 1) & 1;
        if (l > 0)
            k_inproj<<<dim3(16, 32, 4), 256, SM_INPROJ>>>(in_proj_W, l, src);
        k_convxdbl<<<dim3(8, 32, 4), 192, SM_CONVXD>>>(conv_W, conv_b, xproj_W, l,
                                                       trend, sweek, sday, resid);
        k_scan1<<<dim3(CH, BR * BB), 128>>>(A_log, D_skip, dt_W, dt_b, l);
        k_scan2<<<(BR * BB * DD * NN) / 256, 256>>>();
        k_scan3<<<dim3(CH - 1, BR * BB), 128>>>(A_log, dt_W, dt_b, l);
        k_outgemm<<<dim3(8, 32, 4), 256, SM_OUTG>>>(out_W, l, dst,
                                                    trend, sweek, sday, resid);
    }

    k_head<<<dim3(16, 32, 4), 256>>>(outp_W, outp_b, out, LL & 1);
    k_mobius<<<(BB * TT) / 8, 256>>>(out);
}

// round 16
// speedup vs baseline: 1.2717x; 1.0202x over previous
#include <cuda_runtime.h>
#include <cuda_bf16.h>
#include <math.h>

#define BR 4
#define BB 32
#define TT 1024
#define HH 64
#define DD 128
#define NN 16
#define KK 4
#define RR 4
#define EE 32
#define LL 3
#define CH 8           // scan chunks (single-wave occupancy)
#define CS 128         // steps per chunk
#define MAXN 0.996f

typedef unsigned long long u64;

// ---------------- f32x2 packed-FMA helpers (sm_103a FFMA2 path) ----------------
__device__ __forceinline__ u64 pk2(float x, float y) {
    u64 r; asm("mov.b64 %0, {%1, %2};" : "=l"(r) : "f"(x), "f"(y)); return r;
}
__device__ __forceinline__ float2 upk2(u64 v) {
    float2 r; asm("mov.b64 {%0, %1}, %2;" : "=f"(r.x), "=f"(r.y) : "l"(v)); return r;
}
__device__ __forceinline__ void fma2(u64& d, u64 a, u64 b) {
    asm("fma.rn.f32x2 %0, %1, %2, %0;" : "+l"(d) : "l"(a), "l"(b));
}
__device__ __forceinline__ u64 mul2(u64 a, u64 b) {
    u64 r; asm("mul.rn.f32x2 %0, %1, %2;" : "=l"(r) : "l"(a), "l"(b)); return r;
}
__device__ __forceinline__ float ex2f(float x) {
    float r; asm("ex2.approx.f32 %0, %1;" : "=f"(r) : "f"(x)); return r;
}
__device__ __forceinline__ float lg2f(float x) {
    float r; asm("lg2.approx.f32 %0, %1;" : "=f"(r) : "f"(x)); return r;
}
__device__ __forceinline__ float rcpf(float x) {
    float r; asm("rcp.approx.f32 %0, %1;" : "=f"(r) : "f"(x)); return r;
}
#define F_LOG2E 1.4426950408889634f
__device__ __forceinline__ float fsilu(float v) {
    return v * rcpf(1.f + ex2f(-v * F_LOG2E));
}
__device__ __forceinline__ float ftanh(float x) {
    return 1.f - 2.f * rcpf(ex2f(2.f * F_LOG2E * x) + 1.f);
}

union F4U {
    float4 f;
    struct { u64 lo, hi; } d;
};

// ---------------- scratch (device globals; no allocation allowed) ----------------
__device__ float g_h[2][(size_t)BR*BB*TT*HH];
__device__ float g_xr[(size_t)BR*BB*TT*DD];
__device__ float g_z [(size_t)BR*BB*TT*DD];
__device__ float g_u [(size_t)BR*BB*TT*DD];
__device__ float g_xdbl[(size_t)BR*BB*TT*36];
__device__ float g_y [(size_t)BR*BB*TT*DD];
// chunked-scan carries: [bb][chunk][d][n]
__device__ float g_hfin[(size_t)BR*BB*CH*DD*NN];
__device__ float g_pfin[(size_t)BR*BB*CH*DD*NN];
__device__ float g_hin [(size_t)BR*BB*CH*DD*NN];
// rank-1 layer-0 folded weights
__device__ float g_v1[BR * 2 * DD];
__device__ float g_v0[BR * 2 * DD];

__device__ __forceinline__ float wsum(float v) {
    #pragma unroll
    for (int o = 16; o; o >>= 1) v += __shfl_xor_sync(0xffffffffu, v, o);
    return v;
}

// ---------------- k_prep0: fold embed into layer-0 in_proj (rank-1) ----------------
__global__ void k_prep0(const float* __restrict__ inW_all,
                        const float* __restrict__ iW, const float* __restrict__ ib) {
    int br = blockIdx.x, dd = threadIdx.x;
    const float* Wb = inW_all + ((size_t)(br * LL) * 2 * DD + dd) * HH;
    const float* iwp = iW + br * HH;
    const float* ibp = ib + br * HH;
    float v1 = 0.f, v0 = 0.f;
    #pragma unroll
    for (int h = 0; h < HH; h++) {
        float w = Wb[h];
        v1 += iwp[h] * w;
        v0 += ibp[h] * w;
    }
    g_v1[br * 2 * DD + dd] = v1;
    g_v0[br * 2 * DD + dd] = v0;
}

// ---------------- k_inproj: row-packed FFMA2 (layers 1,2) ----------------
__global__ void k_inproj(const float* __restrict__ inW_all, int l, int src) {
    extern __shared__ float sm[];
    float* sHt = sm;              // [64][68] transposed
    float* sW  = sm + 64 * 68;    // [64][132]
    int br = blockIdx.z, b = blockIdx.y, t0 = blockIdx.x * 64;
    int tid = threadIdx.x;
    const float* Wb = inW_all + (size_t)((br * LL + l) * 2 * DD) * HH;
    const float* hb = g_h[src] + ((size_t)(br * BB + b) * TT + t0) * HH;
    for (int i = tid; i < 1024; i += 256) {
        int k = i & 63, rg = i >> 6;
        float h0 = hb[(size_t)(rg * 4 + 0) * HH + k];
        float h1 = hb[(size_t)(rg * 4 + 1) * HH + k];
        float h2 = hb[(size_t)(rg * 4 + 2) * HH + k];
        float h3 = hb[(size_t)(rg * 4 + 3) * HH + k];
        *(float4*)&sHt[k * 68 + rg * 4] = make_float4(h0, h1, h2, h3);
    }

    size_t outbase = ((size_t)(br * BB + b) * TT + t0) * DD;
    int rowg = tid & 7, colg = tid >> 3;
    for (int dc = 0; dc < 2; dc++) {
        __syncthreads();
        int d0 = dc * 128;
        for (int i = tid; i < 2048; i += 256) {
            int k = i & 63, dg = i >> 6;
            float w0 = Wb[(size_t)(d0 + dg * 4 + 0) * HH + k];
            float w1 = Wb[(size_t)(d0 + dg * 4 + 1) * HH + k];
            float w2 = Wb[(size_t)(d0 + dg * 4 + 2) * HH + k];
            float w3 = Wb[(size_t)(d0 + dg * 4 + 3) * HH + k];
            *(float4*)&sW[k * 132 + dg * 4] = make_float4(w0, w1, w2, w3);
        }
        __syncthreads();
        u64 acc[4][4];
        #pragma unroll
        for (int i = 0; i < 4; i++)
            #pragma unroll
            for (int j = 0; j < 4; j++) acc[i][j] = 0ull;
        #pragma unroll 4
        for (int k = 0; k < 64; k++) {
            F4U hA, hB;
            hA.f = *(const float4*)&sHt[k * 68 + rowg * 8];
            hB.f = *(const float4*)&sHt[k * 68 + rowg * 8 + 4];
            u64 rp[4] = {hA.d.lo, hA.d.hi, hB.d.lo, hB.d.hi};
            float4 w = *(const float4*)&sW[k * 132 + colg * 4];
            u64 wb[4] = {pk2(w.x, w.x), pk2(w.y, w.y), pk2(w.z, w.z), pk2(w.w, w.w)};
            #pragma unroll
            for (int i = 0; i < 4; i++)
                #pragma unroll
                for (int j = 0; j < 4; j++)
                    fma2(acc[i][j], rp[i], wb[j]);
        }
        float* dst = (dc == 0) ? g_xr : g_z;
        #pragma unroll
        for (int i = 0; i < 4; i++) {
            float2 c0 = upk2(acc[i][0]), c1 = upk2(acc[i][1]);
            float2 c2 = upk2(acc[i][2]), c3 = upk2(acc[i][3]);
            *(float4*)&dst[outbase + (size_t)(rowg * 8 + 2 * i) * DD + colg * 4] =
                make_float4(c0.x, c1.x, c2.x, c3.x);
            *(float4*)&dst[outbase + (size_t)(rowg * 8 + 2 * i + 1) * DD + colg * 4] =
                make_float4(c0.y, c1.y, c2.y, c3.y);
        }
    }
}

// ---------------- k_convxdbl: fused conv+silu (-> u) + x_dbl GEMM ----------------
__global__ void k_convxdbl(const float* __restrict__ convW, const float* __restrict__ convb,
                           const float* __restrict__ xpW, int l,
                           const float* __restrict__ x0, const float* __restrict__ x1,
                           const float* __restrict__ x2, const float* __restrict__ x3) {
    extern __shared__ float sm[];
    float* sUt = sm;                    // [128][132]
    float* sW  = sm + 128 * 132;        // [128][38]
    float* scw = sW + 128 * 38;         // [128][4]
    float* sb  = scw + 512;             // [128]
    float* sxv = sb + 128;              // [132] (l0)
    float* sv1 = sxv + 132;             // [128] (l0)
    float* sv0 = sv1 + 128;             // [128] (l0)
    int br = blockIdx.z, b = blockIdx.y, t0 = blockIdx.x * 128;
    int tid = threadIdx.x;
    int pl = br * LL + l;
    for (int i = tid; i < 512; i += 192) scw[i] = convW[(size_t)pl * DD * KK + i];
    for (int i = tid; i < 128; i += 192) sb[i] = convb[pl * DD + i];
    if (l == 0) {
        const float* xp = (br == 0) ? x0 : (br == 1) ? x1 : (br == 2) ? x2 : x3;
        for (int i = tid; i < 131; i += 192) {
            int t = t0 - 3 + i;
            sxv[i] = (t >= 0) ? xp[b * TT + t] : 0.f;
        }
        for (int i = tid; i < 128; i += 192) {
            sv1[i] = g_v1[br * 2 * DD + i];
            sv0[i] = g_v0[br * 2 * DD + i];
        }
    }
    __syncthreads();
    size_t rowbase = (size_t)(br * BB + b) * TT;
    if (l == 0) {
        for (int i = tid; i < 4096; i += 192) {
            int rg = i >> 7, d = i & 127;
            float c0 = scw[d * 4 + 0], c1 = scw[d * 4 + 1];
            float c2 = scw[d * 4 + 2], c3 = scw[d * 4 + 3];
            float bias = sb[d];
            float sv1d = sv1[d], sv0d = sv0[d];
            float uu[4];
            size_t gbase = (rowbase + t0 + rg * 4) * DD + d;
            #pragma unroll
            for (int j = 0; j < 4; j++) {
                int r = rg * 4 + j;
                int t = t0 + r;
                float dot = c0 * sxv[r] + c1 * sxv[r + 1] + c2 * sxv[r + 2] + c3 * sxv[r + 3];
                float vs = c3;
                if (t >= 1) vs += c2;
                if (t >= 2) vs += c1;
                if (t >= 3) vs += c0;
                float v = sv1d * dot + sv0d * vs + bias;
                uu[j] = fsilu(v);
                g_u[gbase + (size_t)j * DD] = uu[j];
            }
            *(float4*)&sUt[d * 132 + rg * 4] = make_float4(uu[0], uu[1], uu[2], uu[3]);
        }
    } else {
        for (int i = tid; i < 4096; i += 192) {
            int rg = i >> 7, d = i & 127;
            int tb = t0 + rg * 4;
            float xw[7];
            #pragma unroll
            for (int j = 0; j < 7; j++) {
                int t = tb - 3 + j;
                xw[j] = (t >= 0) ? g_xr[(rowbase + t) * DD + d] : 0.f;
            }
            float c0 = scw[d * 4 + 0], c1 = scw[d * 4 + 1];
            float c2 = scw[d * 4 + 2], c3 = scw[d * 4 + 3];
            float bias = sb[d];
            float uu[4];
            size_t gbase = (rowbase + tb) * DD + d;
            #pragma unroll
            for (int j = 0; j < 4; j++) {
                float v = c0 * xw[j] + c1 * xw[j + 1] + c2 * xw[j + 2] + c3 * xw[j + 3] + bias;
                uu[j] = fsilu(v);
                g_u[gbase + (size_t)j * DD] = uu[j];
            }
            *(float4*)&sUt[d * 132 + rg * 4] = make_float4(uu[0], uu[1], uu[2], uu[3]);
        }
    }
    const float* Wb = xpW + (size_t)pl * 36 * DD;
    for (int i = tid; i < 4608; i += 192) {
        int e = i >> 7, k = i & 127;
        sW[k * 38 + e] = Wb[(size_t)e * DD + k];
    }
    __syncthreads();
    int rowg = tid & 31, colg = tid >> 5;
    u64 acc[4][3];
    #pragma unroll
    for (int r = 0; r < 4; r++)
        #pragma unroll
        for (int p = 0; p < 3; p++) acc[r][p] = 0ull;
    #pragma unroll 2
    for (int k = 0; k < 128; k++) {
        float4 h4 = *(const float4*)&sUt[k * 132 + rowg * 4];
        u64 w0 = *(const u64*)&sW[k * 38 + colg * 6];
        u64 w1 = *(const u64*)&sW[k * 38 + colg * 6 + 2];
        u64 w2 = *(const u64*)&sW[k * 38 + colg * 6 + 4];
        float hv[4] = {h4.x, h4.y, h4.z, h4.w};
        #pragma unroll
        for (int r = 0; r < 4; r++) {
            u64 hp = pk2(hv[r], hv[r]);
            fma2(acc[r][0], hp, w0);
            fma2(acc[r][1], hp, w1);
            fma2(acc[r][2], hp, w2);
        }
    }
    #pragma unroll
    for (int r = 0; r < 4; r++) {
        size_t ob = (rowbase + t0 + rowg * 4 + r) * 36 + colg * 6;
        #pragma unroll
        for (int p = 0; p < 3; p++) {
            float2 v = upk2(acc[r][p]);
            *(float2*)&g_xdbl[ob + 2 * p] = v;
        }
    }
}

// ---------------- k_scan1: per-chunk local scan (h_in = 0), S=sum(dt) for pfin ----------------
__global__ void __launch_bounds__(128, 8)
k_scan1(const float* __restrict__ A_log, const float* __restrict__ Dp_all,
        const float* __restrict__ dtW, const float* __restrict__ dtb, int l) {
    __shared__ float sXD[CS * 40];
    int c = blockIdx.x, bb = blockIdx.y;
    int br = bb >> 5;
    int d = threadIdx.x;
    int pl = br * LL + l;
    const float LN2 = 0.6931471805599453f;
    u64 a2[8];
    #pragma unroll
    for (int p = 0; p < 8; p++) {
        float lo = -__expf(A_log[(size_t)(pl * DD + d) * NN + 2 * p    ]) * F_LOG2E;
        float hi = -__expf(A_log[(size_t)(pl * DD + d) * NN + 2 * p + 1]) * F_LOG2E;
        a2[p] = pk2(lo, hi);
    }
    float dpv = Dp_all[pl * DD + d];
    const float* dw = dtW + (size_t)(pl * DD + d) * RR;
    float w0 = dw[0], w1 = dw[1], w2 = dw[2], w3 = dw[3];
    float db = dtb[pl * DD + d];
    u64 h2[8];
    #pragma unroll
    for (int p = 0; p < 8; p++) h2[p] = 0ull;
    float S = 0.f;
    size_t rowbase = (size_t)bb * TT + (size_t)c * CS;
    for (int i = d; i < CS * 36; i += 128) {
        int rr = i / 36, cc = i - rr * 36;
        sXD[rr * 40 + cc] = g_xdbl[rowbase * 36 + i];
    }
    __syncthreads();
    const float* up = &g_u[rowbase * DD + d];
    float* yp = &g_y[rowbase * DD + d];
    #pragma unroll 1
    for (int sg = 0; sg < CS; sg += 4) {
        float uv[4];
        #pragma unroll
        for (int q = 0; q < 4; q++) uv[q] = up[(sg + q) * DD];
        #pragma unroll
        for (int q = 0; q < 4; q++) {
            int s = sg + q;
            const float* xd = &sXD[s * 40];
            float4 x4 = *(const float4*)xd;
            float dtp = w0 * x4.x + w1 * x4.y + w2 * x4.z + w3 * x4.w + db;
            float e = ex2f(dtp * F_LOG2E);
            float dt = (dtp > 15.f) ? dtp : LN2 * lg2f(1.f + e);
            S += dt;
            float du = dt * uv[q];
            u64 du2 = pk2(du, du);
            u64 dt2 = pk2(dt, dt);
            float y = dpv * uv[q];
            u64 y2 = 0ull;
            #pragma unroll
            for (int p = 0; p < 8; p++) {
                u64 arg = mul2(dt2, a2[p]);
                float2 av = upk2(arg);
                u64 dA2 = pk2(ex2f(av.x), ex2f(av.y));
                u64 B2 = *(const u64*)&xd[4 + 2 * p];
                u64 C2 = *(const u64*)&xd[20 + 2 * p];
                u64 t2 = mul2(du2, B2);
                fma2(t2, dA2, h2[p]);
                h2[p] = t2;
                fma2(y2, t2, C2);
            }
            float2 yv = upk2(y2);
            yp[s * DD] = y + yv.x + yv.y;
        }
    }
    size_t sb = ((size_t)(bb * CH + c) * DD + d) * NN;
    u64 S2 = pk2(S, S);
    #pragma unroll
    for (int p = 0; p < 8; p++) {
        float2 hv = upk2(h2[p]);
        float2 sa = upk2(mul2(S2, a2[p]));
        *(float2*)&g_hfin[sb + 2 * p] = hv;
        *(float2*)&g_pfin[sb + 2 * p] = make_float2(ex2f(sa.x), ex2f(sa.y));
    }
}

// ---------------- k_scan2: sequential combine over chunks -> h_in per chunk ----------------
__global__ void k_scan2() {
    int idx = blockIdx.x * 256 + threadIdx.x;     // (bb*128 + d)*16 + n
    int nd = idx & (DD * NN - 1);
    int bb = idx >> 11;
    size_t base = (size_t)bb * CH * DD * NN + nd;
    float h = 0.f;
    #pragma unroll
    for (int c = 0; c < CH; c++) {
        g_hin[base + (size_t)c * DD * NN] = h;
        h = g_pfin[base + (size_t)c * DD * NN] * h + g_hfin[base + (size_t)c * DD * NN];
    }
}

// ---------------- k_scan3: y += C·(exp(S_t·a) ⊙ h_in), S_t = cumsum(softplus dt) ----------------
__global__ void __launch_bounds__(128, 8)
k_scan3(const float* __restrict__ A_log,
        const float* __restrict__ dtW, const float* __restrict__ dtb, int l) {
    __shared__ float sD[CS * 24];
    int c = blockIdx.x + 1, bb = blockIdx.y;
    int br = bb >> 5;
    int d = threadIdx.x;
    int pl = br * LL + l;
    const float LN2 = 0.6931471805599453f;
    u64 a2[8];
    #pragma unroll
    for (int p = 0; p < 8; p++) {
        float lo = -__expf(A_log[(size_t)(pl * DD + d) * NN + 2 * p    ]) * F_LOG2E;
        float hi = -__expf(A_log[(size_t)(pl * DD + d) * NN + 2 * p + 1]) * F_LOG2E;
        a2[p] = pk2(lo, hi);
    }
    const float* dw = dtW + (size_t)(pl * DD + d) * RR;
    float w0 = dw[0], w1 = dw[1], w2 = dw[2], w3 = dw[3];
    float db = dtb[pl * DD + d];
    size_t sb = ((size_t)(bb * CH + c) * DD + d) * NN;
    u64 hin2[8];
    #pragma unroll
    for (int p = 0; p < 8; p++) hin2[p] = *(const u64*)&g_hin[sb + 2 * p];
    size_t rowbase = (size_t)bb * TT + (size_t)c * CS;
    for (int i = d; i < CS * 20; i += 128) {
        int rr = i / 20, cc = i - rr * 20;
        int src = (cc < 4) ? cc : cc + 16;
        sD[rr * 24 + cc] = g_xdbl[(rowbase + rr) * 36 + src];
    }
    __syncthreads();
    float* yp = &g_y[rowbase * DD + d];
    float S = 0.f;
    #pragma unroll 1
    for (int s = 0; s < CS; s++) {
        const float* xd = &sD[s * 24];
        float4 x4 = *(const float4*)xd;
        float dtp = w0 * x4.x + w1 * x4.y + w2 * x4.z + w3 * x4.w + db;
        float e = ex2f(dtp * F_LOG2E);
        float dt = (dtp > 15.f) ? dtp : LN2 * lg2f(1.f + e);
        S += dt;
        u64 S2 = pk2(S, S);
        u64 y2 = 0ull;
        #pragma unroll
        for (int p = 0; p < 8; p++) {
            u64 arg = mul2(S2, a2[p]);
            float2 av = upk2(arg);
            u64 e2 = pk2(ex2f(av.x), ex2f(av.y));
            u64 c2 = mul2(e2, hin2[p]);
            u64 Cv = *(const u64*)&xd[4 + 2 * p];
            fma2(y2, c2, Cv);
        }
        float2 yv = upk2(y2);
        yp[s * DD] += yv.x + yv.y;
    }
}

// ---------------- k_outgemm (l==0: z synthesized from rank-1 x·v1z+v0z) ----------------
__global__ void k_outgemm(const float* __restrict__ oW, int l, int dst,
                          const float* __restrict__ x0, const float* __restrict__ x1,
                          const float* __restrict__ x2, const float* __restrict__ x3) {
    extern __shared__ float sm[];
    float* sPt = sm;                 // [128][132]
    float* sW  = sm + 128 * 132;     // [128][68]
    float* sxv = sW + 128 * 68;      // [128]  (l0)
    float* sv1z = sxv + 128;         // [128]  (l0)
    float* sv0z = sv1z + 128;        // [128]  (l0)
    int br = blockIdx.z, b = blockIdx.y, t0 = blockIdx.x * 128;
    int tid = threadIdx.x;
    size_t base = ((size_t)(br * BB + b) * TT + t0) * DD;
    if (l == 0) {
        const float* xp = (br == 0) ? x0 : (br == 1) ? x1 : (br == 2) ? x2 : x3;
        for (int i = tid; i < 128; i += 256) {
            sxv[i] = xp[b * TT + t0 + i];
            sv1z[i] = g_v1[br * 2 * DD + DD + i];
            sv0z[i] = g_v0[br * 2 * DD + DD + i];
        }
        __syncthreads();
        for (int i = tid; i < 4096; i += 256) {
            int rg = i >> 7, dd = i & 127;
            size_t gb = base + (size_t)(rg * 4) * DD + dd;
            float v1z = sv1z[dd], v0z = sv0z[dd];
            float p[4];
            #pragma unroll
            for (int j = 0; j < 4; j++) {
                float zv = sxv[rg * 4 + j] * v1z + v0z;
                p[j] = g_y[gb + (size_t)j * DD] * fsilu(zv);
            }
            *(float4*)&sPt[dd * 132 + rg * 4] = make_float4(p[0], p[1], p[2], p[3]);
        }
    } else {
        for (int i = tid; i < 4096; i += 256) {
            int rg = i >> 7, dd = i & 127;
            size_t gb = base + (size_t)(rg * 4) * DD + dd;
            float p[4];
            #pragma unroll
            for (int j = 0; j < 4; j++) {
                float zv = g_z[gb + (size_t)j * DD];
                p[j] = g_y[gb + (size_t)j * DD] * fsilu(zv);
            }
            *(float4*)&sPt[dd * 132 + rg * 4] = make_float4(p[0], p[1], p[2], p[3]);
        }
    }
    const float* Wb = oW + (size_t)(br * LL + l) * HH * DD;
    for (int i = tid; i < 2048; i += 256) {
        int k = i & 127, hg = i >> 7;
        float w0 = Wb[(size_t)(hg * 4 + 0) * DD + k];
        float w1 = Wb[(size_t)(hg * 4 + 1) * DD + k];
        float w2 = Wb[(size_t)(hg * 4 + 2) * DD + k];
        float w3 = Wb[(size_t)(hg * 4 + 3) * DD + k];
        *(float4*)&sW[k * 68 + hg * 4] = make_float4(w0, w1, w2, w3);
    }
    __syncthreads();
    int rowg = tid & 31, colg = tid >> 5;
    u64 acc[4][4];
    #pragma unroll
    for (int r = 0; r < 4; r++)
        #pragma unroll
        for (int p = 0; p < 4; p++) acc[r][p] = 0ull;
    #pragma unroll 2
    for (int k = 0; k < 128; k++) {
        float4 h4 = *(const float4*)&sPt[k * 132 + rowg * 4];
        u64 w0 = *(const u64*)&sW[k * 68 + colg * 8];
        u64 w1 = *(const u64*)&sW[k * 68 + colg * 8 + 2];
        u64 w2 = *(const u64*)&sW[k * 68 + colg * 8 + 4];
        u64 w3 = *(const u64*)&sW[k * 68 + colg * 8 + 6];
        float hv[4] = {h4.x, h4.y, h4.z, h4.w};
        #pragma unroll
        for (int r = 0; r < 4; r++) {
            u64 hp = pk2(hv[r], hv[r]);
            fma2(acc[r][0], hp, w0);
            fma2(acc[r][1], hp, w1);
            fma2(acc[r][2], hp, w2);
            fma2(acc[r][3], hp, w3);
        }
    }
    float* hb = g_h[dst] + ((size_t)(br * BB + b) * TT + t0) * HH;
    #pragma unroll
    for (int r = 0; r < 4; r++) {
        int row = rowg * 4 + r;
        float2 p0 = upk2(acc[r][0]), p1 = upk2(acc[r][1]);
        float2 p2 = upk2(acc[r][2]), p3 = upk2(acc[r][3]);
        *(float4*)&hb[(size_t)row * HH + colg * 8]     = make_float4(p0.x, p0.y, p1.x, p1.y);
        *(float4*)&hb[(size_t)row * HH + colg * 8 + 4] = make_float4(p2.x, p2.y, p3.x, p3.y);
    }
}

// ---------------- k_head ----------------
__global__ void k_head(const float* __restrict__ opW, const float* __restrict__ opb,
                       float* __restrict__ out, int src) {
    __shared__ float sH[64 * 64];
    __shared__ float sW[64 * 33];
    __shared__ float sB[32];
    int br = blockIdx.z, b = blockIdx.y, t0 = blockIdx.x * 64;
    int tid = threadIdx.x;
    const float* hb = g_h[src] + ((size_t)(br * BB + b) * TT + t0) * HH;
    for (int i = tid; i < 4096; i += 256) sH[i] = hb[i];
    for (int i = tid; i < 2048; i += 256) {
        int e = i >> 6, hh = i & 63;
        sW[hh * 33 + e] = opW[(size_t)br * EE * HH + i];
    }
    if (tid < 32) sB[tid] = opb[br * EE + tid];
    __syncthreads();
    int e = tid & 31, rg = tid >> 5;
    #pragma unroll
    for (int i = 0; i < 8; i++) {
        int r = rg * 8 + i;
        float acc = sB[e];
        #pragma unroll
        for (int hh = 0; hh < 64; hh++) acc += sH[r * 64 + hh] * sW[hh * 33 + e];
        float z = ftanh(acc);
        float n2 = wsum(z * z);
        float n = sqrtf(fmaxf(n2, 1e-15f));
        float zh = z * ftanh(n) * rcpf(n);
        float n2b = wsum(zh * zh);
        float nb = sqrtf(fmaxf(n2b, 1e-15f));
        if (nb > MAXN) zh *= MAXN * rcpf(nb);
        out[(size_t)br * BB * TT * EE + ((size_t)(b * TT + t0 + r)) * EE + e] = zh;
    }
}

// ---------------- k_mobius ----------------
__device__ __forceinline__ float mob(float x, float y) {
    float x2 = wsum(x * x);
    float y2 = wsum(y * y);
    float xy = wsum(x * y);
    float num = (1.f + 2.f * xy + y2) * x + (1.f - x2) * y;
    float den = 1.f + 2.f * xy + x2 * y2;
    return num * rcpf(fmaxf(den, 1e-15f));
}

__global__ void k_mobius(float* __restrict__ out) {
    int warp = threadIdx.x >> 5, e = threadIdx.x & 31;
    size_t row = (size_t)blockIdx.x * 8 + warp;
    size_t S = (size_t)BB * TT * EE;
    float tv = out[0 * S + row * EE + e];
    float wv = out[1 * S + row * EE + e];
    float dv = out[2 * S + row * EE + e];
    float rv = out[3 * S + row * EE + e];
    float m = mob(wv, dv);
    m = mob(tv, m);
    m = mob(m, rv);
    float n2 = wsum(m * m);
    float n = sqrtf(fmaxf(n2, 1e-15f));
    if (n > MAXN) m *= MAXN * rcpf(n);
    out[4 * S + row * EE + e] = m;
}

// ---------------- launch ----------------
extern "C" void kernel_launch(void* const* d_in, const int* in_sizes, int n_in,
                              void* d_out, int out_size) {
    const float* trend = (const float*)d_in[0];
    const float* sweek = (const float*)d_in[1];
    const float* sday  = (const float*)d_in[2];
    const float* resid = (const float*)d_in[3];
    const float* inp_W = (const float*)d_in[4];
    const float* inp_b = (const float*)d_in[5];
    const float* in_proj_W = (const float*)d_in[6];
    const float* conv_W = (const float*)d_in[7];
    const float* conv_b = (const float*)d_in[8];
    const float* xproj_W = (const float*)d_in[9];
    const float* dt_W = (const float*)d_in[10];
    const float* dt_b = (const float*)d_in[11];
    const float* A_log = (const float*)d_in[12];
    const float* D_skip = (const float*)d_in[13];
    const float* out_W = (const float*)d_in[14];
    const float* outp_W = (const float*)d_in[15];
    const float* outp_b = (const float*)d_in[16];
    float* out = (float*)d_out;

    const int SM_INPROJ = (64 * 68 + 64 * 132) * 4;
    const int SM_CONVXD = (128 * 132 + 128 * 38 + 512 + 128 + 132 + 256) * 4;
    const int SM_OUTG   = (128 * 132 + 128 * 68 + 384) * 4;
    cudaFuncSetAttribute(k_inproj,   cudaFuncAttributeMaxDynamicSharedMemorySize, SM_INPROJ);
    cudaFuncSetAttribute(k_convxdbl, cudaFuncAttributeMaxDynamicSharedMemorySize, SM_CONVXD);
    cudaFuncSetAttribute(k_outgemm,  cudaFuncAttributeMaxDynamicSharedMemorySize, SM_OUTG);

    k_prep0<<<BR, 256>>>(in_proj_W, inp_W, inp_b);

    for (int l = 0; l < LL; l++) {
        int src = l & 1, dst = (l + 1) & 1;
        if (l > 0)
            k_inproj<<<dim3(16, 32, 4), 256, SM_INPROJ>>>(in_proj_W, l, src);
        k_convxdbl<<<dim3(8, 32, 4), 192, SM_CONVXD>>>(conv_W, conv_b, xproj_W, l,
                                                       trend, sweek, sday, resid);
        k_scan1<<<dim3(CH, BR * BB), 128>>>(A_log, D_skip, dt_W, dt_b, l);
        k_scan2<<<(BR * BB * DD * NN) / 256, 256>>>();
        k_scan3<<<dim3(CH - 1, BR * BB), 128>>>(A_log, dt_W, dt_b, l);
        k_outgemm<<<dim3(8, 32, 4), 256, SM_OUTG>>>(out_W, l, dst,
                                                    trend, sweek, sday, resid);
    }

    k_head<<<dim3(16, 32, 4), 256>>>(outp_W, outp_b, out, LL & 1);
    k_mobius<<<(BB * TT) / 8, 256>>>(out);
}

// round 17
// speedup vs baseline: 1.2790x; 1.0057x over previous
#include <cuda_runtime.h>
#include <cuda_bf16.h>
#include <math.h>

#define BR 4
#define BB 32
#define TT 1024
#define HH 64
#define DD 128
#define NN 16
#define KK 4
#define RR 4
#define EE 32
#define LL 3
#define CH 8           // scan chunks (single-wave occupancy)
#define CS 128         // steps per chunk
#define MAXN 0.996f

typedef unsigned long long u64;

// ---------------- f32x2 packed-FMA helpers (sm_103a FFMA2 path) ----------------
__device__ __forceinline__ u64 pk2(float x, float y) {
    u64 r; asm("mov.b64 %0, {%1, %2};" : "=l"(r) : "f"(x), "f"(y)); return r;
}
__device__ __forceinline__ float2 upk2(u64 v) {
    float2 r; asm("mov.b64 {%0, %1}, %2;" : "=f"(r.x), "=f"(r.y) : "l"(v)); return r;
}
__device__ __forceinline__ void fma2(u64& d, u64 a, u64 b) {
    asm("fma.rn.f32x2 %0, %1, %2, %0;" : "+l"(d) : "l"(a), "l"(b));
}
__device__ __forceinline__ u64 mul2(u64 a, u64 b) {
    u64 r; asm("mul.rn.f32x2 %0, %1, %2;" : "=l"(r) : "l"(a), "l"(b)); return r;
}
__device__ __forceinline__ float ex2f(float x) {
    float r; asm("ex2.approx.f32 %0, %1;" : "=f"(r) : "f"(x)); return r;
}
__device__ __forceinline__ float lg2f(float x) {
    float r; asm("lg2.approx.f32 %0, %1;" : "=f"(r) : "f"(x)); return r;
}
__device__ __forceinline__ float rcpf(float x) {
    float r; asm("rcp.approx.f32 %0, %1;" : "=f"(r) : "f"(x)); return r;
}
#define F_LOG2E 1.4426950408889634f
__device__ __forceinline__ float fsilu(float v) {
    return v * rcpf(1.f + ex2f(-v * F_LOG2E));
}
__device__ __forceinline__ float ftanh(float x) {
    return 1.f - 2.f * rcpf(ex2f(2.f * F_LOG2E * x) + 1.f);
}

union F4U {
    float4 f;
    struct { u64 lo, hi; } d;
};

// ---------------- scratch (device globals; no allocation allowed) ----------------
__device__ float g_h[2][(size_t)BR*BB*TT*HH];
__device__ float g_xr[(size_t)BR*BB*TT*DD];
__device__ float g_z [(size_t)BR*BB*TT*DD];
__device__ float g_u [(size_t)BR*BB*TT*DD];
__device__ float g_xdbl[(size_t)BR*BB*TT*36];
__device__ float g_y [(size_t)BR*BB*TT*DD];
// chunked-scan carries: [bb][chunk][d][n]
__device__ float g_hfin[(size_t)BR*BB*CH*DD*NN];
__device__ float g_pfin[(size_t)BR*BB*CH*DD*NN];
__device__ float g_hin [(size_t)BR*BB*CH*DD*NN];
// rank-1 layer-0 folded weights
__device__ float g_v1[BR * 2 * DD];
__device__ float g_v0[BR * 2 * DD];

__device__ __forceinline__ float wsum(float v) {
    #pragma unroll
    for (int o = 16; o; o >>= 1) v += __shfl_xor_sync(0xffffffffu, v, o);
    return v;
}

// ---------------- k_prep0: fold embed into layer-0 in_proj (rank-1) ----------------
__global__ void k_prep0(const float* __restrict__ inW_all,
                        const float* __restrict__ iW, const float* __restrict__ ib) {
    int br = blockIdx.x, dd = threadIdx.x;
    const float* Wb = inW_all + ((size_t)(br * LL) * 2 * DD + dd) * HH;
    const float* iwp = iW + br * HH;
    const float* ibp = ib + br * HH;
    float v1 = 0.f, v0 = 0.f;
    #pragma unroll
    for (int h = 0; h < HH; h++) {
        float w = Wb[h];
        v1 += iwp[h] * w;
        v0 += ibp[h] * w;
    }
    g_v1[br * 2 * DD + dd] = v1;
    g_v0[br * 2 * DD + dd] = v0;
}

// ---------------- k_inproj: row-packed FFMA2 (layers 1,2) ----------------
__global__ void k_inproj(const float* __restrict__ inW_all, int l, int src) {
    extern __shared__ float sm[];
    float* sHt = sm;              // [64][68] transposed
    float* sW  = sm + 64 * 68;    // [64][132]
    int br = blockIdx.z, b = blockIdx.y, t0 = blockIdx.x * 64;
    int tid = threadIdx.x;
    const float* Wb = inW_all + (size_t)((br * LL + l) * 2 * DD) * HH;
    const float* hb = g_h[src] + ((size_t)(br * BB + b) * TT + t0) * HH;
    for (int i = tid; i < 1024; i += 256) {
        int k = i & 63, rg = i >> 6;
        float h0 = hb[(size_t)(rg * 4 + 0) * HH + k];
        float h1 = hb[(size_t)(rg * 4 + 1) * HH + k];
        float h2 = hb[(size_t)(rg * 4 + 2) * HH + k];
        float h3 = hb[(size_t)(rg * 4 + 3) * HH + k];
        *(float4*)&sHt[k * 68 + rg * 4] = make_float4(h0, h1, h2, h3);
    }

    size_t outbase = ((size_t)(br * BB + b) * TT + t0) * DD;
    int rowg = tid & 7, colg = tid >> 3;
    for (int dc = 0; dc < 2; dc++) {
        __syncthreads();
        int d0 = dc * 128;
        for (int i = tid; i < 2048; i += 256) {
            int k = i & 63, dg = i >> 6;
            float w0 = Wb[(size_t)(d0 + dg * 4 + 0) * HH + k];
            float w1 = Wb[(size_t)(d0 + dg * 4 + 1) * HH + k];
            float w2 = Wb[(size_t)(d0 + dg * 4 + 2) * HH + k];
            float w3 = Wb[(size_t)(d0 + dg * 4 + 3) * HH + k];
            *(float4*)&sW[k * 132 + dg * 4] = make_float4(w0, w1, w2, w3);
        }
        __syncthreads();
        u64 acc[4][4];
        #pragma unroll
        for (int i = 0; i < 4; i++)
            #pragma unroll
            for (int j = 0; j < 4; j++) acc[i][j] = 0ull;
        #pragma unroll 4
        for (int k = 0; k < 64; k++) {
            F4U hA, hB;
            hA.f = *(const float4*)&sHt[k * 68 + rowg * 8];
            hB.f = *(const float4*)&sHt[k * 68 + rowg * 8 + 4];
            u64 rp[4] = {hA.d.lo, hA.d.hi, hB.d.lo, hB.d.hi};
            float4 w = *(const float4*)&sW[k * 132 + colg * 4];
            u64 wb[4] = {pk2(w.x, w.x), pk2(w.y, w.y), pk2(w.z, w.z), pk2(w.w, w.w)};
            #pragma unroll
            for (int i = 0; i < 4; i++)
                #pragma unroll
                for (int j = 0; j < 4; j++)
                    fma2(acc[i][j], rp[i], wb[j]);
        }
        float* dst = (dc == 0) ? g_xr : g_z;
        #pragma unroll
        for (int i = 0; i < 4; i++) {
            float2 c0 = upk2(acc[i][0]), c1 = upk2(acc[i][1]);
            float2 c2 = upk2(acc[i][2]), c3 = upk2(acc[i][3]);
            *(float4*)&dst[outbase + (size_t)(rowg * 8 + 2 * i) * DD + colg * 4] =
                make_float4(c0.x, c1.x, c2.x, c3.x);
            *(float4*)&dst[outbase + (size_t)(rowg * 8 + 2 * i + 1) * DD + colg * 4] =
                make_float4(c0.y, c1.y, c2.y, c3.y);
        }
    }
}

// ---------------- k_convxdbl: fused conv+silu (-> u) + x_dbl GEMM ----------------
__global__ void k_convxdbl(const float* __restrict__ convW, const float* __restrict__ convb,
                           const float* __restrict__ xpW, int l,
                           const float* __restrict__ x0, const float* __restrict__ x1,
                           const float* __restrict__ x2, const float* __restrict__ x3) {
    extern __shared__ float sm[];
    float* sUt = sm;                    // [128][132]
    float* sW  = sm + 128 * 132;        // [128][38]
    float* scw = sW + 128 * 38;         // [128][4]
    float* sb  = scw + 512;             // [128]
    float* sxv = sb + 128;              // [132] (l0)
    float* sv1 = sxv + 132;             // [128] (l0)
    float* sv0 = sv1 + 128;             // [128] (l0)
    int br = blockIdx.z, b = blockIdx.y, t0 = blockIdx.x * 128;
    int tid = threadIdx.x;
    int pl = br * LL + l;
    for (int i = tid; i < 512; i += 192) scw[i] = convW[(size_t)pl * DD * KK + i];
    for (int i = tid; i < 128; i += 192) sb[i] = convb[pl * DD + i];
    if (l == 0) {
        const float* xp = (br == 0) ? x0 : (br == 1) ? x1 : (br == 2) ? x2 : x3;
        for (int i = tid; i < 131; i += 192) {
            int t = t0 - 3 + i;
            sxv[i] = (t >= 0) ? xp[b * TT + t] : 0.f;
        }
        for (int i = tid; i < 128; i += 192) {
            sv1[i] = g_v1[br * 2 * DD + i];
            sv0[i] = g_v0[br * 2 * DD + i];
        }
    }
    __syncthreads();
    size_t rowbase = (size_t)(br * BB + b) * TT;
    if (l == 0) {
        for (int i = tid; i < 4096; i += 192) {
            int rg = i >> 7, d = i & 127;
            float c0 = scw[d * 4 + 0], c1 = scw[d * 4 + 1];
            float c2 = scw[d * 4 + 2], c3 = scw[d * 4 + 3];
            float bias = sb[d];
            float sv1d = sv1[d], sv0d = sv0[d];
            float uu[4];
            size_t gbase = (rowbase + t0 + rg * 4) * DD + d;
            #pragma unroll
            for (int j = 0; j < 4; j++) {
                int r = rg * 4 + j;
                int t = t0 + r;
                float dot = c0 * sxv[r] + c1 * sxv[r + 1] + c2 * sxv[r + 2] + c3 * sxv[r + 3];
                float vs = c3;
                if (t >= 1) vs += c2;
                if (t >= 2) vs += c1;
                if (t >= 3) vs += c0;
                float v = sv1d * dot + sv0d * vs + bias;
                uu[j] = fsilu(v);
                g_u[gbase + (size_t)j * DD] = uu[j];
            }
            *(float4*)&sUt[d * 132 + rg * 4] = make_float4(uu[0], uu[1], uu[2], uu[3]);
        }
    } else {
        for (int i = tid; i < 4096; i += 192) {
            int rg = i >> 7, d = i & 127;
            int tb = t0 + rg * 4;
            float xw[7];
            #pragma unroll
            for (int j = 0; j < 7; j++) {
                int t = tb - 3 + j;
                xw[j] = (t >= 0) ? g_xr[(rowbase + t) * DD + d] : 0.f;
            }
            float c0 = scw[d * 4 + 0], c1 = scw[d * 4 + 1];
            float c2 = scw[d * 4 + 2], c3 = scw[d * 4 + 3];
            float bias = sb[d];
            float uu[4];
            size_t gbase = (rowbase + tb) * DD + d;
            #pragma unroll
            for (int j = 0; j < 4; j++) {
                float v = c0 * xw[j] + c1 * xw[j + 1] + c2 * xw[j + 2] + c3 * xw[j + 3] + bias;
                uu[j] = fsilu(v);
                g_u[gbase + (size_t)j * DD] = uu[j];
            }
            *(float4*)&sUt[d * 132 + rg * 4] = make_float4(uu[0], uu[1], uu[2], uu[3]);
        }
    }
    const float* Wb = xpW + (size_t)pl * 36 * DD;
    for (int i = tid; i < 4608; i += 192) {
        int e = i >> 7, k = i & 127;
        sW[k * 38 + e] = Wb[(size_t)e * DD + k];
    }
    __syncthreads();
    int rowg = tid & 31, colg = tid >> 5;
    u64 acc[4][3];
    #pragma unroll
    for (int r = 0; r < 4; r++)
        #pragma unroll
        for (int p = 0; p < 3; p++) acc[r][p] = 0ull;
    #pragma unroll 2
    for (int k = 0; k < 128; k++) {
        float4 h4 = *(const float4*)&sUt[k * 132 + rowg * 4];
        u64 w0 = *(const u64*)&sW[k * 38 + colg * 6];
        u64 w1 = *(const u64*)&sW[k * 38 + colg * 6 + 2];
        u64 w2 = *(const u64*)&sW[k * 38 + colg * 6 + 4];
        float hv[4] = {h4.x, h4.y, h4.z, h4.w};
        #pragma unroll
        for (int r = 0; r < 4; r++) {
            u64 hp = pk2(hv[r], hv[r]);
            fma2(acc[r][0], hp, w0);
            fma2(acc[r][1], hp, w1);
            fma2(acc[r][2], hp, w2);
        }
    }
    #pragma unroll
    for (int r = 0; r < 4; r++) {
        size_t ob = (rowbase + t0 + rowg * 4 + r) * 36 + colg * 6;
        #pragma unroll
        for (int p = 0; p < 3; p++) {
            float2 v = upk2(acc[r][p]);
            *(float2*)&g_xdbl[ob + 2 * p] = v;
        }
    }
}

// ---------------- k_scan1: per-chunk local scan (h_in = 0), S=sum(dt) for pfin ----------------
__global__ void __launch_bounds__(128, 8)
k_scan1(const float* __restrict__ A_log, const float* __restrict__ Dp_all,
        const float* __restrict__ dtW, const float* __restrict__ dtb, int l) {
    __shared__ float sXD[CS * 40];
    int c = blockIdx.x, bb = blockIdx.y;
    int br = bb >> 5;
    int d = threadIdx.x;
    int pl = br * LL + l;
    const float LN2 = 0.6931471805599453f;
    u64 a2[8];
    #pragma unroll
    for (int p = 0; p < 8; p++) {
        float lo = -__expf(A_log[(size_t)(pl * DD + d) * NN + 2 * p    ]) * F_LOG2E;
        float hi = -__expf(A_log[(size_t)(pl * DD + d) * NN + 2 * p + 1]) * F_LOG2E;
        a2[p] = pk2(lo, hi);
    }
    float dpv = Dp_all[pl * DD + d];
    const float* dw = dtW + (size_t)(pl * DD + d) * RR;
    float w0 = dw[0], w1 = dw[1], w2 = dw[2], w3 = dw[3];
    float db = dtb[pl * DD + d];
    u64 h2[8];
    #pragma unroll
    for (int p = 0; p < 8; p++) h2[p] = 0ull;
    float S = 0.f;
    size_t rowbase = (size_t)bb * TT + (size_t)c * CS;
    for (int i = d; i < CS * 36; i += 128) {
        int rr = i / 36, cc = i - rr * 36;
        sXD[rr * 40 + cc] = g_xdbl[rowbase * 36 + i];
    }
    __syncthreads();
    const float* up = &g_u[rowbase * DD + d];
    float* yp = &g_y[rowbase * DD + d];
    #pragma unroll 1
    for (int sg = 0; sg < CS; sg += 4) {
        float uv[4];
        #pragma unroll
        for (int q = 0; q < 4; q++) uv[q] = up[(sg + q) * DD];
        #pragma unroll
        for (int q = 0; q < 4; q++) {
            int s = sg + q;
            const float* xd = &sXD[s * 40];
            float4 x4 = *(const float4*)xd;
            float dtp = w0 * x4.x + w1 * x4.y + w2 * x4.z + w3 * x4.w + db;
            float e = ex2f(dtp * F_LOG2E);
            float dt = (dtp > 15.f) ? dtp : LN2 * lg2f(1.f + e);
            S += dt;
            float du = dt * uv[q];
            u64 du2 = pk2(du, du);
            u64 dt2 = pk2(dt, dt);
            float y = dpv * uv[q];
            u64 y2 = 0ull;
            #pragma unroll
            for (int p = 0; p < 8; p++) {
                u64 arg = mul2(dt2, a2[p]);
                float2 av = upk2(arg);
                u64 dA2 = pk2(ex2f(av.x), ex2f(av.y));
                u64 B2 = *(const u64*)&xd[4 + 2 * p];
                u64 C2 = *(const u64*)&xd[20 + 2 * p];
                u64 t2 = mul2(du2, B2);
                fma2(t2, dA2, h2[p]);
                h2[p] = t2;
                fma2(y2, t2, C2);
            }
            float2 yv = upk2(y2);
            yp[s * DD] = y + yv.x + yv.y;
        }
    }
    size_t sb = ((size_t)(bb * CH + c) * DD + d) * NN;
    u64 S2 = pk2(S, S);
    #pragma unroll
    for (int p = 0; p < 8; p++) {
        float2 hv = upk2(h2[p]);
        float2 sa = upk2(mul2(S2, a2[p]));
        *(float2*)&g_hfin[sb + 2 * p] = hv;
        *(float2*)&g_pfin[sb + 2 * p] = make_float2(ex2f(sa.x), ex2f(sa.y));
    }
}

// ---------------- k_scan2: sequential combine over chunks -> h_in per chunk ----------------
__global__ void k_scan2() {
    int idx = blockIdx.x * 256 + threadIdx.x;     // (bb*128 + d)*16 + n
    int nd = idx & (DD * NN - 1);
    int bb = idx >> 11;
    size_t base = (size_t)bb * CH * DD * NN + nd;
    float h = 0.f;
    #pragma unroll
    for (int c = 0; c < CH; c++) {
        g_hin[base + (size_t)c * DD * NN] = h;
        h = g_pfin[base + (size_t)c * DD * NN] * h + g_hfin[base + (size_t)c * DD * NN];
    }
}

// ---------------- k_scan3: y += C·(exp(S_t·a) ⊙ h_in), S_t = cumsum(softplus dt) ----------------
__global__ void __launch_bounds__(128, 8)
k_scan3(const float* __restrict__ A_log,
        const float* __restrict__ dtW, const float* __restrict__ dtb, int l) {
    __shared__ float sD[CS * 24];
    int c = blockIdx.x + 1, bb = blockIdx.y;
    int br = bb >> 5;
    int d = threadIdx.x;
    int pl = br * LL + l;
    const float LN2 = 0.6931471805599453f;
    u64 a2[8];
    #pragma unroll
    for (int p = 0; p < 8; p++) {
        float lo = -__expf(A_log[(size_t)(pl * DD + d) * NN + 2 * p    ]) * F_LOG2E;
        float hi = -__expf(A_log[(size_t)(pl * DD + d) * NN + 2 * p + 1]) * F_LOG2E;
        a2[p] = pk2(lo, hi);
    }
    const float* dw = dtW + (size_t)(pl * DD + d) * RR;
    float w0 = dw[0], w1 = dw[1], w2 = dw[2], w3 = dw[3];
    float db = dtb[pl * DD + d];
    size_t sb = ((size_t)(bb * CH + c) * DD + d) * NN;
    u64 hin2[8];
    #pragma unroll
    for (int p = 0; p < 8; p++) hin2[p] = *(const u64*)&g_hin[sb + 2 * p];
    size_t rowbase = (size_t)bb * TT + (size_t)c * CS;
    for (int i = d; i < CS * 20; i += 128) {
        int rr = i / 20, cc = i - rr * 20;
        int src = (cc < 4) ? cc : cc + 16;
        sD[rr * 24 + cc] = g_xdbl[(rowbase + rr) * 36 + src];
    }
    __syncthreads();
    float* yp = &g_y[rowbase * DD + d];
    float S = 0.f;
    #pragma unroll 1
    for (int s = 0; s < CS; s++) {
        const float* xd = &sD[s * 24];
        float4 x4 = *(const float4*)xd;
        float dtp = w0 * x4.x + w1 * x4.y + w2 * x4.z + w3 * x4.w + db;
        float e = ex2f(dtp * F_LOG2E);
        float dt = (dtp > 15.f) ? dtp : LN2 * lg2f(1.f + e);
        S += dt;
        u64 S2 = pk2(S, S);
        u64 y2 = 0ull;
        #pragma unroll
        for (int p = 0; p < 8; p++) {
            u64 arg = mul2(S2, a2[p]);
            float2 av = upk2(arg);
            u64 e2 = pk2(ex2f(av.x), ex2f(av.y));
            u64 c2 = mul2(e2, hin2[p]);
            u64 Cv = *(const u64*)&xd[4 + 2 * p];
            fma2(y2, c2, Cv);
        }
        float2 yv = upk2(y2);
        yp[s * DD] += yv.x + yv.y;
    }
}

// ---------------- k_outgemm (l==0: z synthesized from rank-1 x·v1z+v0z) ----------------
__global__ void k_outgemm(const float* __restrict__ oW, int l, int dst,
                          const float* __restrict__ x0, const float* __restrict__ x1,
                          const float* __restrict__ x2, const float* __restrict__ x3) {
    extern __shared__ float sm[];
    float* sPt = sm;                 // [128][132]
    float* sW  = sm + 128 * 132;     // [128][68]
    float* sxv = sW + 128 * 68;      // [128]  (l0)
    float* sv1z = sxv + 128;         // [128]  (l0)
    float* sv0z = sv1z + 128;        // [128]  (l0)
    int br = blockIdx.z, b = blockIdx.y, t0 = blockIdx.x * 128;
    int tid = threadIdx.x;
    size_t base = ((size_t)(br * BB + b) * TT + t0) * DD;
    if (l == 0) {
        const float* xp = (br == 0) ? x0 : (br == 1) ? x1 : (br == 2) ? x2 : x3;
        for (int i = tid; i < 128; i += 256) {
            sxv[i] = xp[b * TT + t0 + i];
            sv1z[i] = g_v1[br * 2 * DD + DD + i];
            sv0z[i] = g_v0[br * 2 * DD + DD + i];
        }
        __syncthreads();
        for (int i = tid; i < 4096; i += 256) {
            int rg = i >> 7, dd = i & 127;
            size_t gb = base + (size_t)(rg * 4) * DD + dd;
            float v1z = sv1z[dd], v0z = sv0z[dd];
            float p[4];
            #pragma unroll
            for (int j = 0; j < 4; j++) {
                float zv = sxv[rg * 4 + j] * v1z + v0z;
                p[j] = g_y[gb + (size_t)j * DD] * fsilu(zv);
            }
            *(float4*)&sPt[dd * 132 + rg * 4] = make_float4(p[0], p[1], p[2], p[3]);
        }
    } else {
        for (int i = tid; i < 4096; i += 256) {
            int rg = i >> 7, dd = i & 127;
            size_t gb = base + (size_t)(rg * 4) * DD + dd;
            float p[4];
            #pragma unroll
            for (int j = 0; j < 4; j++) {
                float zv = g_z[gb + (size_t)j * DD];
                p[j] = g_y[gb + (size_t)j * DD] * fsilu(zv);
            }
            *(float4*)&sPt[dd * 132 + rg * 4] = make_float4(p[0], p[1], p[2], p[3]);
        }
    }
    const float* Wb = oW + (size_t)(br * LL + l) * HH * DD;
    for (int i = tid; i < 2048; i += 256) {
        int k = i & 127, hg = i >> 7;
        float w0 = Wb[(size_t)(hg * 4 + 0) * DD + k];
        float w1 = Wb[(size_t)(hg * 4 + 1) * DD + k];
        float w2 = Wb[(size_t)(hg * 4 + 2) * DD + k];
        float w3 = Wb[(size_t)(hg * 4 + 3) * DD + k];
        *(float4*)&sW[k * 68 + hg * 4] = make_float4(w0, w1, w2, w3);
    }
    __syncthreads();
    int rowg = tid & 31, colg = tid >> 5;
    u64 acc[4][4];
    #pragma unroll
    for (int r = 0; r < 4; r++)
        #pragma unroll
        for (int p = 0; p < 4; p++) acc[r][p] = 0ull;
    #pragma unroll 2
    for (int k = 0; k < 128; k++) {
        float4 h4 = *(const float4*)&sPt[k * 132 + rowg * 4];
        u64 w0 = *(const u64*)&sW[k * 68 + colg * 8];
        u64 w1 = *(const u64*)&sW[k * 68 + colg * 8 + 2];
        u64 w2 = *(const u64*)&sW[k * 68 + colg * 8 + 4];
        u64 w3 = *(const u64*)&sW[k * 68 + colg * 8 + 6];
        float hv[4] = {h4.x, h4.y, h4.z, h4.w};
        #pragma unroll
        for (int r = 0; r < 4; r++) {
            u64 hp = pk2(hv[r], hv[r]);
            fma2(acc[r][0], hp, w0);
            fma2(acc[r][1], hp, w1);
            fma2(acc[r][2], hp, w2);
            fma2(acc[r][3], hp, w3);
        }
    }
    float* hb = g_h[dst] + ((size_t)(br * BB + b) * TT + t0) * HH;
    #pragma unroll
    for (int r = 0; r < 4; r++) {
        int row = rowg * 4 + r;
        float2 p0 = upk2(acc[r][0]), p1 = upk2(acc[r][1]);
        float2 p2 = upk2(acc[r][2]), p3 = upk2(acc[r][3]);
        *(float4*)&hb[(size_t)row * HH + colg * 8]     = make_float4(p0.x, p0.y, p1.x, p1.y);
        *(float4*)&hb[(size_t)row * HH + colg * 8 + 4] = make_float4(p2.x, p2.y, p3.x, p3.y);
    }
}

// ---------------- k_head ----------------
__global__ void k_head(const float* __restrict__ opW, const float* __restrict__ opb,
                       float* __restrict__ out, int src) {
    __shared__ float sH[64 * 64];
    __shared__ float sW[64 * 33];
    __shared__ float sB[32];
    int br = blockIdx.z, b = blockIdx.y, t0 = blockIdx.x * 64;
    int tid = threadIdx.x;
    const float* hb = g_h[src] + ((size_t)(br * BB + b) * TT + t0) * HH;
    for (int i = tid; i < 4096; i += 256) sH[i] = hb[i];
    for (int i = tid; i < 2048; i += 256) {
        int e = i >> 6, hh = i & 63;
        sW[hh * 33 + e] = opW[(size_t)br * EE * HH + i];
    }
    if (tid < 32) sB[tid] = opb[br * EE + tid];
    __syncthreads();
    int e = tid & 31, rg = tid >> 5;
    #pragma unroll
    for (int i = 0; i < 8; i++) {
        int r = rg * 8 + i;
        float acc = sB[e];
        #pragma unroll
        for (int hh = 0; hh < 64; hh++) acc += sH[r * 64 + hh] * sW[hh * 33 + e];
        float z = ftanh(acc);
        float n2 = wsum(z * z);
        float n = sqrtf(fmaxf(n2, 1e-15f));
        float zh = z * ftanh(n) * rcpf(n);
        float n2b = wsum(zh * zh);
        float nb = sqrtf(fmaxf(n2b, 1e-15f));
        if (nb > MAXN) zh *= MAXN * rcpf(nb);
        out[(size_t)br * BB * TT * EE + ((size_t)(b * TT + t0 + r)) * EE + e] = zh;
    }
}

// ---------------- k_mobius ----------------
__device__ __forceinline__ float mob(float x, float y) {
    float x2 = wsum(x * x);
    float y2 = wsum(y * y);
    float xy = wsum(x * y);
    float num = (1.f + 2.f * xy + y2) * x + (1.f - x2) * y;
    float den = 1.f + 2.f * xy + x2 * y2;
    return num * rcpf(fmaxf(den, 1e-15f));
}

__global__ void k_mobius(float* __restrict__ out) {
    int warp = threadIdx.x >> 5, e = threadIdx.x & 31;
    size_t row = (size_t)blockIdx.x * 8 + warp;
    size_t S = (size_t)BB * TT * EE;
    float tv = out[0 * S + row * EE + e];
    float wv = out[1 * S + row * EE + e];
    float dv = out[2 * S + row * EE + e];
    float rv = out[3 * S + row * EE + e];
    float m = mob(wv, dv);
    m = mob(tv, m);
    m = mob(m, rv);
    float n2 = wsum(m * m);
    float n = sqrtf(fmaxf(n2, 1e-15f));
    if (n > MAXN) m *= MAXN * rcpf(n);
    out[4 * S + row * EE + e] = m;
}

// ---------------- launch ----------------
extern "C" void kernel_launch(void* const* d_in, const int* in_sizes, int n_in,
                              void* d_out, int out_size) {
    const float* trend = (const float*)d_in[0];
    const float* sweek = (const float*)d_in[1];
    const float* sday  = (const float*)d_in[2];
    const float* resid = (const float*)d_in[3];
    const float* inp_W = (const float*)d_in[4];
    const float* inp_b = (const float*)d_in[5];
    const float* in_proj_W = (const float*)d_in[6];
    const float* conv_W = (const float*)d_in[7];
    const float* conv_b = (const float*)d_in[8];
    const float* xproj_W = (const float*)d_in[9];
    const float* dt_W = (const float*)d_in[10];
    const float* dt_b = (const float*)d_in[11];
    const float* A_log = (const float*)d_in[12];
    const float* D_skip = (const float*)d_in[13];
    const float* out_W = (const float*)d_in[14];
    const float* outp_W = (const float*)d_in[15];
    const float* outp_b = (const float*)d_in[16];
    float* out = (float*)d_out;

    const int SM_INPROJ = (64 * 68 + 64 * 132) * 4;
    const int SM_CONVXD = (128 * 132 + 128 * 38 + 512 + 128 + 132 + 256) * 4;
    const int SM_OUTG   = (128 * 132 + 128 * 68 + 384) * 4;
    cudaFuncSetAttribute(k_inproj,   cudaFuncAttributeMaxDynamicSharedMemorySize, SM_INPROJ);
    cudaFuncSetAttribute(k_convxdbl, cudaFuncAttributeMaxDynamicSharedMemorySize, SM_CONVXD);
    cudaFuncSetAttribute(k_outgemm,  cudaFuncAttributeMaxDynamicSharedMemorySize, SM_OUTG);

    k_prep0<<<BR, 256>>>(in_proj_W, inp_W, inp_b);

    for (int l = 0; l < LL; l++) {
        int src = l & 1, dst = (l + 1) & 1;
        if (l > 0)
            k_inproj<<<dim3(16, 32, 4), 256, SM_INPROJ>>>(in_proj_W, l, src);
        k_convxdbl<<<dim3(8, 32, 4), 192, SM_CONVXD>>>(conv_W, conv_b, xproj_W, l,
                                                       trend, sweek, sday, resid);
        k_scan1<<<dim3(CH, BR * BB), 128>>>(A_log, D_skip, dt_W, dt_b, l);
        k_scan2<<<(BR * BB * DD * NN) / 256, 256>>>();
        k_scan3<<<dim3(CH - 1, BR * BB), 128>>>(A_log, dt_W, dt_b, l);
        k_outgemm<<<dim3(8, 32, 4), 256, SM_OUTG>>>(out_W, l, dst,
                                                    trend, sweek, sday, resid);
    }

    k_head<<<dim3(16, 32, 4), 256>>>(outp_W, outp_b, out, LL & 1);
    k_mobius<<<(BB * TT) / 8, 256>>>(out);
}